// round 11
// baseline (speedup 1.0000x reference)
#include <cuda_runtime.h>
#include <cuda_fp16.h>
#include <cstdint>

#define MTOK 8192
#define HID  2048
#define DEX  4096
#define RK   64
#define K1P  HID       // 2048  GEMM1 K (plain fp16 both sides)
#define K2P  DEX       // 4096  GEMM2 K (plain fp16 both sides)
#define KRE  (2*RK)    // 128   LoRA tail K (split pairs)
#define SPLITK 4
// scaling: A-side stored = 16*true, B-side = 64*true, GEMM raw = 1024*true
#define INV_GEMM (1.0f/1024.0f)

// ---------------- scratch (device globals) ----------------------------------
__device__ __align__(16) __half g_Xe  [(size_t)MTOK * K1P];
__device__ __align__(16) __half g_Wgue[(size_t)2*DEX * K1P];
__device__ __align__(16) __half g_Ague[(size_t)RK * K1P];
__device__ __align__(16) __half g_Bgue[(size_t)2*DEX * KRE];
__device__ __align__(16) __half g_Wde [(size_t)HID * K2P];
__device__ __align__(16) __half g_Ade [(size_t)RK * K2P];
__device__ __align__(16) __half g_Bde [(size_t)HID * KRE];
__device__ __align__(16) float  g_Pk  [(size_t)SPLITK * MTOK * RK];
__device__ __align__(16) __half g_T1e [(size_t)MTOK * KRE];
__device__ __align__(16) __half g_T2e [(size_t)MTOK * KRE];
__device__ __align__(16) __half g_He  [(size_t)MTOK * K2P];

// ---------------- fp32 -> fp16 split pair (B-dup) for LoRA tails ------------
template<bool ASIDE>
__global__ void cvt_expand8(const float* __restrict__ in,
                            __half* __restrict__ out,
                            size_t n8, float scale) {
    size_t i = (size_t)blockIdx.x * blockDim.x + threadIdx.x;
    if (i >= n8) return;
    const float4* p = reinterpret_cast<const float4*>(in) + i * 2;
    float4 v0 = p[0], v1 = p[1];
    float x[8] = {v0.x, v0.y, v0.z, v0.w, v1.x, v1.y, v1.z, v1.w};
    __half ob[16];
#pragma unroll
    for (int k = 0; k < 8; k++) {
        float xv = x[k] * scale;
        __half hi = __float2half_rn(xv);
        ob[2*k] = hi;
        if (ASIDE) ob[2*k+1] = __float2half_rn(xv - __half2float(hi));
        else       ob[2*k+1] = hi;
    }
    uint4* o = reinterpret_cast<uint4*>(out + i * 16);
    const uint4* s = reinterpret_cast<const uint4*>(ob);
    o[0] = s[0]; o[1] = s[1];
}

// ---------------- fp32 -> plain fp16 (8 elems/thread) -----------------------
__global__ void cvt_plain8(const float* __restrict__ in,
                           __half* __restrict__ out,
                           size_t n8, float scale) {
    size_t i = (size_t)blockIdx.x * blockDim.x + threadIdx.x;
    if (i >= n8) return;
    const float4* p = reinterpret_cast<const float4*>(in) + i * 2;
    float4 v0 = p[0], v1 = p[1];
    float x[8] = {v0.x, v0.y, v0.z, v0.w, v1.x, v1.y, v1.z, v1.w};
    __half ob[8];
#pragma unroll
    for (int k = 0; k < 8; k++) ob[k] = __float2half_rn(x[k] * scale);
    *reinterpret_cast<uint4*>(out + i * 8) = *reinterpret_cast<const uint4*>(ob);
}

// ---------------- splitK reduce + scale + A-side fp16 pair ------------------
__global__ void reduce_expand(const float* __restrict__ P,
                              __half* __restrict__ out) {
    size_t idx = (size_t)blockIdx.x * blockDim.x + threadIdx.x;
    if (idx >= (size_t)MTOK * RK) return;
    const size_t S = (size_t)MTOK * RK;
    float s = (P[idx] + P[idx + S] + P[idx + 2*S] + P[idx + 3*S]) * (1.0f/256.0f);
    __half hi = __float2half_rn(s);
    out[2*idx]   = hi;
    out[2*idx+1] = __float2half_rn(s - __half2float(hi));
}

// ============================================================================
// WIDE kernel: CTA 128x256, 8 warps of 64x64.  MODE 0: C fp32 (descaled) +
// LoRA tail.  MODE 1: fused SwiGLU -> He plain fp16 (x16), gate/up interleaved
// B rows (tile covers 128 d, n0 = d-offset).
// ============================================================================
#define BMW 128
#define BNW 256
#define STG_W 4
#define ATILE_W (BMW * 64 * 2)        // 16 KB
#define BTILE_W (BNW * 64 * 2)        // 32 KB
#define SMEM_W (STG_W * (ATILE_W + BTILE_W))   // 192 KB

template<int MODE>
__device__ __forceinline__ void load_tiles_w(uint32_t smem_u32, int stage,
                                             const __half* gA,
                                             const __half* gB,
                                             int m0, int n0, int Ks,
                                             int kt, int tid) {
#pragma unroll
    for (int i = 0; i < 12; i++) {
        int c = tid + i * 256;          // 0..3071 16B chunks
        int row = c >> 3;
        int col = c & 7;
        if (row < BMW) {
            uint32_t sw = (uint32_t)(col ^ (row & 7)) << 4;
            uint32_t da = smem_u32 + (uint32_t)stage * ATILE_W + row * 128 + sw;
            const void* sa = (const void*)(gA + (size_t)(m0 + row) * Ks
                                              + (size_t)kt * 64 + col * 8);
            asm volatile("cp.async.cg.shared.global [%0], [%1], 16;"
                         :: "r"(da), "l"(sa));
        } else {
            int r = row - BMW;          // 0..255
            int brow;
            if (MODE == 1) {            // gate/up interleave; n0 = d-offset
                brow = (r & 1) ? (DEX + n0 + (r >> 1)) : (n0 + (r >> 1));
            } else {
                brow = n0 + r;
            }
            uint32_t sw = (uint32_t)(col ^ (r & 7)) << 4;
            uint32_t db = smem_u32 + (uint32_t)(STG_W * ATILE_W)
                                   + (uint32_t)stage * BTILE_W + r * 128 + sw;
            const void* sb = (const void*)(gB + (size_t)brow * Ks
                                              + (size_t)kt * 64 + col * 8);
            asm volatile("cp.async.cg.shared.global [%0], [%1], 16;"
                         :: "r"(db), "l"(sb));
        }
    }
}

template<int MODE>
__global__ __launch_bounds__(256, 1) void gemm_wide(
    const __half* __restrict__ A,  const __half* __restrict__ B,
    const __half* __restrict__ A2, const __half* __restrict__ B2,
    void* __restrict__ Cout, int N, int K, int Kt) {
    extern __shared__ char smem[];
    const uint32_t smem_u32 = (uint32_t)__cvta_generic_to_shared(smem);
    const int tid  = threadIdx.x;
    const int warp = tid >> 5, lane = tid & 31;
    const int wm = warp >> 2, wn = warp & 3;   // 2x4 warps of 64x64
    const int gid = lane >> 2, tig = lane & 3;

    // grouped CTA swizzle (8 y-tiles per x step) for L2 reuse of B panels
    int bx = blockIdx.x, by = blockIdx.y;
    if (gridDim.x > 1) {
        const int GRP = 8;
        int lin = by * gridDim.x + bx;
        int per = gridDim.x * GRP;
        int g   = lin / per, rem = lin % per;
        int gy  = g * GRP;
        int h   = gridDim.y - gy; if (h > GRP) h = GRP;
        by = gy + rem % h;
        bx = rem / h;
    }
    const int m0 = by * BMW;
    const int n0 = bx * ((MODE == 1) ? 128 : BNW);

    float acc[4][8][4];
#pragma unroll
    for (int a = 0; a < 4; a++)
#pragma unroll
        for (int b = 0; b < 8; b++)
#pragma unroll
            for (int c = 0; c < 4; c++) acc[a][b][c] = 0.0f;

    const int a_row_in = (lane & 15);
    const int a_ch_in  = (lane >> 4);
    const int b_row_in = ((lane >> 4) << 3) + (lane & 7);
    const int b_ch_in  = ((lane >> 3) & 1);

    for (int seg = 0; seg < 2; seg++) {
        const __half* gA = seg ? A2 : A;
        const __half* gB = seg ? B2 : B;
        const int Ks = seg ? Kt : K;
        if (Ks == 0) break;
        const int ktiles = Ks / 64;

        for (int p = 0; p < STG_W - 1; p++) {
            if (p < ktiles)
                load_tiles_w<MODE>(smem_u32, p, gA, gB, m0, n0, Ks, p, tid);
            asm volatile("cp.async.commit_group;");
        }

        for (int kt = 0; kt < ktiles; kt++) {
            asm volatile("cp.async.wait_group %0;" :: "n"(STG_W - 2));
            __syncthreads();

            const int st = kt % STG_W;
            const uint32_t sA = smem_u32 + (uint32_t)st * ATILE_W;
            const uint32_t sB = smem_u32 + (uint32_t)(STG_W * ATILE_W)
                                         + (uint32_t)st * BTILE_W;

            uint32_t ra[4][4], rb[8][2];
            auto frags = [&](int kk) {
#pragma unroll
                for (int mi = 0; mi < 4; mi++) {
                    int row = wm * 64 + mi * 16 + a_row_in;
                    int ch  = (kk >> 3) + a_ch_in;
                    uint32_t ad = sA + row * 128 + ((uint32_t)(ch ^ (row & 7)) << 4);
                    asm volatile(
                        "ldmatrix.sync.aligned.m8n8.x4.shared.b16 {%0,%1,%2,%3}, [%4];"
                        : "=r"(ra[mi][0]), "=r"(ra[mi][1]),
                          "=r"(ra[mi][2]), "=r"(ra[mi][3])
                        : "r"(ad));
                }
#pragma unroll
                for (int p = 0; p < 4; p++) {
                    int row = wn * 64 + p * 16 + b_row_in;
                    int ch  = (kk >> 3) + b_ch_in;
                    uint32_t bd = sB + row * 128 + ((uint32_t)(ch ^ (row & 7)) << 4);
                    asm volatile(
                        "ldmatrix.sync.aligned.m8n8.x4.shared.b16 {%0,%1,%2,%3}, [%4];"
                        : "=r"(rb[2*p][0]), "=r"(rb[2*p][1]),
                          "=r"(rb[2*p+1][0]), "=r"(rb[2*p+1][1])
                        : "r"(bd));
                }
            };
            auto mmas = [&]() {
#pragma unroll
                for (int mi = 0; mi < 4; mi++)
#pragma unroll
                    for (int ni = 0; ni < 8; ni++)
                        asm volatile(
                            "mma.sync.aligned.m16n8k16.row.col.f32.f16.f16.f32 "
                            "{%0,%1,%2,%3}, {%4,%5,%6,%7}, {%8,%9}, {%0,%1,%2,%3};"
                            : "+f"(acc[mi][ni][0]), "+f"(acc[mi][ni][1]),
                              "+f"(acc[mi][ni][2]), "+f"(acc[mi][ni][3])
                            : "r"(ra[mi][0]), "r"(ra[mi][1]),
                              "r"(ra[mi][2]), "r"(ra[mi][3]),
                              "r"(rb[ni][0]), "r"(rb[ni][1]));
            };

            frags(0);
            mmas();
            int nk = kt + STG_W - 1;
            if (nk < ktiles)
                load_tiles_w<MODE>(smem_u32, nk % STG_W, gA, gB, m0, n0, Ks,
                                   nk, tid);
            asm volatile("cp.async.commit_group;");
#pragma unroll
            for (int kk = 16; kk < 64; kk += 16) { frags(kk); mmas(); }
        }
        asm volatile("cp.async.wait_group 0;");
        __syncthreads();
    }

    if (MODE == 0) {
        float* C = (float*)Cout;
#pragma unroll
        for (int mi = 0; mi < 4; mi++) {
            int r0 = m0 + wm * 64 + mi * 16 + gid;
#pragma unroll
            for (int ni = 0; ni < 8; ni++) {
                int c0 = n0 + wn * 64 + ni * 8 + tig * 2;
                float2 v0 = make_float2(acc[mi][ni][0] * INV_GEMM,
                                        acc[mi][ni][1] * INV_GEMM);
                float2 v1 = make_float2(acc[mi][ni][2] * INV_GEMM,
                                        acc[mi][ni][3] * INV_GEMM);
                *reinterpret_cast<float2*>(C + (size_t)r0 * N + c0) = v0;
                *reinterpret_cast<float2*>(C + (size_t)(r0 + 8) * N + c0) = v1;
            }
        }
    } else {
        // MODE 1: acc pair (c0,c1) = (gate,up) raw; local d = wn*32+ni*4+tig
        float* hs = reinterpret_cast<float*>(smem);   // [128][132] padded
#pragma unroll
        for (int mi = 0; mi < 4; mi++) {
            int rl = wm * 64 + mi * 16 + gid;
#pragma unroll
            for (int ni = 0; ni < 8; ni++) {
                int dl = wn * 32 + ni * 4 + tig;      // 0..127
                float g0 = acc[mi][ni][0] * INV_GEMM, u0 = acc[mi][ni][1] * INV_GEMM;
                hs[rl * 132 + dl]       = u0 * g0 / (1.0f + __expf(-g0));
                float g1 = acc[mi][ni][2] * INV_GEMM, u1 = acc[mi][ni][3] * INV_GEMM;
                hs[(rl + 8) * 132 + dl] = u1 * g1 / (1.0f + __expf(-g1));
            }
        }
        __syncthreads();
        __half* He = (__half*)Cout;
#pragma unroll
        for (int it = 0; it < 8; it++) {
            int rl = it * 16 + (tid >> 4);
            int d0 = (tid & 15) * 8;
            float4 v0 = *reinterpret_cast<float4*>(&hs[rl * 132 + d0]);
            float4 v1 = *reinterpret_cast<float4*>(&hs[rl * 132 + d0 + 4]);
            float x[8] = {v0.x, v0.y, v0.z, v0.w, v1.x, v1.y, v1.z, v1.w};
            __half ob[8];
#pragma unroll
            for (int k = 0; k < 8; k++)
                ob[k] = __float2half_rn(x[k] * 16.0f);    // A-side scale
            *reinterpret_cast<uint4*>(
                He + (size_t)(m0 + rl) * K2P + (n0 + d0)) =
                *reinterpret_cast<const uint4*>(ob);
        }
    }
}

// ============================================================================
// LoRA splitK kernel (proven 128x128, 64x32 warps): raw partials to Pk.
// ============================================================================
#define BM 128
#define BN 128
#define STAGES 3
#define NTH 256
#define TILE_BYTES (BM * 64 * 2)               // 16 KB
#define SMEM_BYTES (2 * STAGES * TILE_BYTES)   // 96 KB

__device__ __forceinline__ void load_tiles_l(uint32_t smem_u32, int stage,
                                             const __half* gA,
                                             const __half* gB,
                                             int m0, int Ks, int kt, int tid) {
#pragma unroll
    for (int i = 0; i < 4; i++) {
        int c = tid + i * NTH;
        int row = c >> 3;
        int col = c & 7;
        uint32_t sw = (uint32_t)(col ^ (row & 7)) << 4;
        uint32_t da = smem_u32 + (uint32_t)stage * TILE_BYTES + row * 128 + sw;
        const void* sa = (const void*)(gA + (size_t)(m0 + row) * Ks
                                          + (size_t)kt * 64 + col * 8);
        asm volatile("cp.async.cg.shared.global [%0], [%1], 16;"
                     :: "r"(da), "l"(sa));
        int brow = row < RK ? row : RK - 1;     // clamp (N=64)
        uint32_t db = smem_u32 + (uint32_t)(STAGES + stage) * TILE_BYTES
                               + row * 128 + sw;
        const void* sb = (const void*)(gB + (size_t)brow * Ks
                                          + (size_t)kt * 64 + col * 8);
        asm volatile("cp.async.cg.shared.global [%0], [%1], 16;"
                     :: "r"(db), "l"(sb));
    }
}

__global__ __launch_bounds__(NTH, 2) void gemm_lora(
    const __half* __restrict__ A, const __half* __restrict__ B,
    float* __restrict__ Cout, int K) {
    extern __shared__ char smem[];
    const uint32_t smem_u32 = (uint32_t)__cvta_generic_to_shared(smem);
    const int tid  = threadIdx.x;
    const int warp = tid >> 5, lane = tid & 31;
    const int wm = warp >> 2, wn = warp & 3;
    const int gid = lane >> 2, tig = lane & 3;
    const int m0 = blockIdx.y * BM;

    float acc[4][4][4];
#pragma unroll
    for (int a = 0; a < 4; a++)
#pragma unroll
        for (int b = 0; b < 4; b++)
#pragma unroll
            for (int c = 0; c < 4; c++) acc[a][b][c] = 0.0f;

    const int a_row_in = (lane & 15);
    const int a_ch_in  = (lane >> 4);
    const int b_row_in = ((lane >> 4) << 3) + (lane & 7);
    const int b_ch_in  = ((lane >> 3) & 1);

    const int cps  = (K / 64) / SPLITK;
    const int koff = blockIdx.z * cps;

    for (int p = 0; p < STAGES - 1; p++) {
        if (p < cps)
            load_tiles_l(smem_u32, p, A, B, m0, K, koff + p, tid);
        asm volatile("cp.async.commit_group;");
    }
    for (int kt = 0; kt < cps; kt++) {
        asm volatile("cp.async.wait_group %0;" :: "n"(STAGES - 2));
        __syncthreads();
        int nk = kt + STAGES - 1;
        if (nk < cps)
            load_tiles_l(smem_u32, nk % STAGES, A, B, m0, K, koff + nk, tid);
        asm volatile("cp.async.commit_group;");

        const int st = kt % STAGES;
        const uint32_t sA = smem_u32 + (uint32_t)st * TILE_BYTES;
        const uint32_t sB = smem_u32 + (uint32_t)(STAGES + st) * TILE_BYTES;
#pragma unroll
        for (int kk = 0; kk < 64; kk += 16) {
            uint32_t ra[4][4], rb[4][2];
#pragma unroll
            for (int mi = 0; mi < 4; mi++) {
                int row = wm * 64 + mi * 16 + a_row_in;
                int ch  = (kk >> 3) + a_ch_in;
                uint32_t ad = sA + row * 128 + ((uint32_t)(ch ^ (row & 7)) << 4);
                asm volatile(
                    "ldmatrix.sync.aligned.m8n8.x4.shared.b16 {%0,%1,%2,%3}, [%4];"
                    : "=r"(ra[mi][0]), "=r"(ra[mi][1]),
                      "=r"(ra[mi][2]), "=r"(ra[mi][3])
                    : "r"(ad));
            }
#pragma unroll
            for (int p = 0; p < 2; p++) {
                int row = wn * 32 + p * 16 + b_row_in;
                int ch  = (kk >> 3) + b_ch_in;
                uint32_t bd = sB + row * 128 + ((uint32_t)(ch ^ (row & 7)) << 4);
                asm volatile(
                    "ldmatrix.sync.aligned.m8n8.x4.shared.b16 {%0,%1,%2,%3}, [%4];"
                    : "=r"(rb[2*p][0]), "=r"(rb[2*p][1]),
                      "=r"(rb[2*p+1][0]), "=r"(rb[2*p+1][1])
                    : "r"(bd));
            }
#pragma unroll
            for (int mi = 0; mi < 4; mi++)
#pragma unroll
                for (int ni = 0; ni < 4; ni++)
                    asm volatile(
                        "mma.sync.aligned.m16n8k16.row.col.f32.f16.f16.f32 "
                        "{%0,%1,%2,%3}, {%4,%5,%6,%7}, {%8,%9}, {%0,%1,%2,%3};"
                        : "+f"(acc[mi][ni][0]), "+f"(acc[mi][ni][1]),
                          "+f"(acc[mi][ni][2]), "+f"(acc[mi][ni][3])
                        : "r"(ra[mi][0]), "r"(ra[mi][1]),
                          "r"(ra[mi][2]), "r"(ra[mi][3]),
                          "r"(rb[ni][0]), "r"(rb[ni][1]));
        }
    }
    asm volatile("cp.async.wait_group 0;");
    __syncthreads();

    float* C = Cout + (size_t)blockIdx.z * MTOK * RK;
#pragma unroll
    for (int mi = 0; mi < 4; mi++) {
        int r0 = m0 + wm * 64 + mi * 16 + gid;
#pragma unroll
        for (int ni = 0; ni < 4; ni++) {
            int c0 = wn * 32 + ni * 8 + tig * 2;
            if (c0 < RK) {
                float2 v0 = make_float2(acc[mi][ni][0], acc[mi][ni][1]);
                float2 v1 = make_float2(acc[mi][ni][2], acc[mi][ni][3]);
                *reinterpret_cast<float2*>(C + (size_t)r0 * RK + c0) = v0;
                *reinterpret_cast<float2*>(C + (size_t)(r0 + 8) * RK + c0) = v1;
            }
        }
    }
}

// ---------------- launcher ---------------------------------------------------
extern "C" void kernel_launch(void* const* d_in, const int* in_sizes, int n_in,
                              void* d_out, int out_size) {
    const float* X   = (const float*)d_in[0];
    const float* Wgu = (const float*)d_in[1];
    const float* Agu = (const float*)d_in[2];
    const float* Bgu = (const float*)d_in[3];
    const float* Wd  = (const float*)d_in[4];
    const float* Ad  = (const float*)d_in[5];
    const float* Bd  = (const float*)d_in[6];
    float* out = (float*)d_out;

    __half *Xe, *Wgue, *Ague, *Bgue, *Wde, *Ade, *Bde, *T1e, *T2e, *He;
    float *Pk;
    cudaGetSymbolAddress((void**)&Xe,   g_Xe);
    cudaGetSymbolAddress((void**)&Wgue, g_Wgue);
    cudaGetSymbolAddress((void**)&Ague, g_Ague);
    cudaGetSymbolAddress((void**)&Bgue, g_Bgue);
    cudaGetSymbolAddress((void**)&Wde,  g_Wde);
    cudaGetSymbolAddress((void**)&Ade,  g_Ade);
    cudaGetSymbolAddress((void**)&Bde,  g_Bde);
    cudaGetSymbolAddress((void**)&Pk,   g_Pk);
    cudaGetSymbolAddress((void**)&T1e,  g_T1e);
    cudaGetSymbolAddress((void**)&T2e,  g_T2e);
    cudaGetSymbolAddress((void**)&He,   g_He);

    cudaFuncSetAttribute(gemm_wide<0>,
                         cudaFuncAttributeMaxDynamicSharedMemorySize, SMEM_W);
    cudaFuncSetAttribute(gemm_wide<1>,
                         cudaFuncAttributeMaxDynamicSharedMemorySize, SMEM_W);
    cudaFuncSetAttribute(gemm_lora,
                         cudaFuncAttributeMaxDynamicSharedMemorySize, SMEM_BYTES);

    const int T = 256;
    auto g8 = [&](size_t n) { return (unsigned)((n / 8 + T - 1) / T); };

    // big operands plain fp16: A-side scale 16, B-side scale 64
    { size_t n = (size_t)MTOK * HID;
      cvt_plain8<<<g8(n), T>>>(X, Xe, n/8, 16.0f); }
    { size_t n = (size_t)2 * DEX * HID;
      cvt_plain8<<<g8(n), T>>>(Wgu, Wgue, n/8, 64.0f); }
    { size_t n = (size_t)RK * HID;
      cvt_plain8<<<g8(n), T>>>(Agu, Ague, n/8, 64.0f); }
    { size_t n = (size_t)HID * DEX;
      cvt_plain8<<<g8(n), T>>>(Wd, Wde, n/8, 64.0f); }
    { size_t n = (size_t)RK * DEX;
      cvt_plain8<<<g8(n), T>>>(Ad, Ade, n/8, 64.0f); }
    // LoRA B tails keep split-pair expansion (B-dup form)
    { size_t n = (size_t)2 * DEX * RK;
      cvt_expand8<false><<<g8(n), T>>>(Bgu, Bgue, n/8, 64.0f); }
    { size_t n = (size_t)HID * RK;
      cvt_expand8<false><<<g8(n), T>>>(Bd, Bde, n/8, 64.0f); }

    const unsigned gr = (unsigned)(((size_t)MTOK * RK + T - 1) / T);

    // T1 raw = 1024*(X @ Agu^T), splitK x4 -> reduce(/256) -> T1e pairs
    gemm_lora<<<dim3(1, MTOK/BM, SPLITK), NTH, SMEM_BYTES>>>(Xe, Ague, Pk, K1P);
    reduce_expand<<<gr, T>>>(Pk, T1e);

    // He = 16*swiglu(X@Wgu^T + 0.25*T1@Bgu^T), plain fp16 (wide tile)
    gemm_wide<1><<<dim3(DEX/128, MTOK/BMW), 256, SMEM_W>>>(
        Xe, Wgue, T1e, Bgue, He, 2*DEX, K1P, KRE);

    // T2 raw = 1024*(H @ Ad^T), splitK x4 -> reduce -> T2e
    gemm_lora<<<dim3(1, MTOK/BM, SPLITK), NTH, SMEM_BYTES>>>(He, Ade, Pk, K2P);
    reduce_expand<<<gr, T>>>(Pk, T2e);

    // out = H@Wd^T + 0.25*T2@Bd^T (wide tile)
    gemm_wide<0><<<dim3(HID/BNW, MTOK/BMW), 256, SMEM_W>>>(
        He, Wde, T2e, Bde, out, HID, K2P, KRE);
}

// round 12
// speedup vs baseline: 1.1261x; 1.1261x over previous
#include <cuda_runtime.h>
#include <cuda_fp16.h>
#include <cstdint>

#define MTOK 8192
#define HID  2048
#define DEX  4096
#define RK   64
#define K1P  HID       // 2048  GEMM1 K (plain fp16 both sides)
#define K2P  DEX       // 4096  GEMM2 K (plain fp16 both sides)
#define KRE  (2*RK)    // 128   LoRA tail K (split pairs)
#define SPLITK 4
// scaling: A-side stored = 16*true, B-side = 64*true, GEMM raw = 1024*true
#define INV_GEMM (1.0f/1024.0f)

// ---------------- scratch (device globals) ----------------------------------
__device__ __align__(16) __half g_Xe  [(size_t)MTOK * K1P];
__device__ __align__(16) __half g_Wgue[(size_t)2*DEX * K1P];
__device__ __align__(16) __half g_Ague[(size_t)RK * K1P];
__device__ __align__(16) __half g_Bgue[(size_t)2*DEX * KRE];
__device__ __align__(16) __half g_Wde [(size_t)HID * K2P];
__device__ __align__(16) __half g_Ade [(size_t)RK * K2P];
__device__ __align__(16) __half g_Bde [(size_t)HID * KRE];
__device__ __align__(16) float  g_Pk  [(size_t)SPLITK * MTOK * RK];
__device__ __align__(16) __half g_T1e [(size_t)MTOK * KRE];
__device__ __align__(16) __half g_T2e [(size_t)MTOK * KRE];
__device__ __align__(16) __half g_He  [(size_t)MTOK * K2P];

// ---------------- fp32 -> fp16 split pair (B-dup) for LoRA tails ------------
template<bool ASIDE>
__global__ void cvt_expand8(const float* __restrict__ in,
                            __half* __restrict__ out,
                            size_t n8, float scale) {
    size_t i = (size_t)blockIdx.x * blockDim.x + threadIdx.x;
    if (i >= n8) return;
    const float4* p = reinterpret_cast<const float4*>(in) + i * 2;
    float4 v0 = p[0], v1 = p[1];
    float x[8] = {v0.x, v0.y, v0.z, v0.w, v1.x, v1.y, v1.z, v1.w};
    __half ob[16];
#pragma unroll
    for (int k = 0; k < 8; k++) {
        float xv = x[k] * scale;
        __half hi = __float2half_rn(xv);
        ob[2*k] = hi;
        if (ASIDE) ob[2*k+1] = __float2half_rn(xv - __half2float(hi));
        else       ob[2*k+1] = hi;
    }
    uint4* o = reinterpret_cast<uint4*>(out + i * 16);
    const uint4* s = reinterpret_cast<const uint4*>(ob);
    o[0] = s[0]; o[1] = s[1];
}

// ---------------- fp32 -> plain fp16 (8 elems/thread) -----------------------
__global__ void cvt_plain8(const float* __restrict__ in,
                           __half* __restrict__ out,
                           size_t n8, float scale) {
    size_t i = (size_t)blockIdx.x * blockDim.x + threadIdx.x;
    if (i >= n8) return;
    const float4* p = reinterpret_cast<const float4*>(in) + i * 2;
    float4 v0 = p[0], v1 = p[1];
    float x[8] = {v0.x, v0.y, v0.z, v0.w, v1.x, v1.y, v1.z, v1.w};
    __half ob[8];
#pragma unroll
    for (int k = 0; k < 8; k++) ob[k] = __float2half_rn(x[k] * scale);
    *reinterpret_cast<uint4*>(out + i * 8) = *reinterpret_cast<const uint4*>(ob);
}

// ---------------- splitK reduce + scale + A-side fp16 pair ------------------
__global__ void reduce_expand(const float* __restrict__ P,
                              __half* __restrict__ out) {
    size_t idx = (size_t)blockIdx.x * blockDim.x + threadIdx.x;
    if (idx >= (size_t)MTOK * RK) return;
    const size_t S = (size_t)MTOK * RK;
    float s = (P[idx] + P[idx + S] + P[idx + 2*S] + P[idx + 3*S]) * (1.0f/256.0f);
    __half hi = __float2half_rn(s);
    out[2*idx]   = hi;
    out[2*idx+1] = __float2half_rn(s - __half2float(hi));
}

// ============================================================================
// SQ kernel: CTA 128x128, 4 warps (2x2) of 64x64, 128 threads, 2 CTAs/SM.
// MODE 0: C fp32 (descaled) + LoRA tail.  MODE 1: fused SwiGLU -> He plain
// fp16 (x16), gate/up interleaved B rows (tile covers 64 d, n0 = d-offset).
// ============================================================================
#define BMS 128
#define BNS 128
#define STG_S 3
#define NTH_S 128
#define TILE_S (128 * 64 * 2)                  // 16 KB
#define SMEM_S (2 * STG_S * TILE_S)            // 96 KB

template<int MODE>
__device__ __forceinline__ void load_tiles_s(uint32_t smem_u32, int stage,
                                             const __half* gA,
                                             const __half* gB,
                                             int m0, int n0, int Ks,
                                             int kt, int tid) {
#pragma unroll
    for (int i = 0; i < 8; i++) {
        int c = tid + i * NTH_S;        // 0..1023 16B chunks per operand
        int row = c >> 3;
        int col = c & 7;
        uint32_t sw = (uint32_t)(col ^ (row & 7)) << 4;
        uint32_t da = smem_u32 + (uint32_t)stage * TILE_S + row * 128 + sw;
        const void* sa = (const void*)(gA + (size_t)(m0 + row) * Ks
                                          + (size_t)kt * 64 + col * 8);
        asm volatile("cp.async.cg.shared.global [%0], [%1], 16;"
                     :: "r"(da), "l"(sa));
        int brow;
        if (MODE == 1) {                // gate/up interleave; n0 = d-offset
            brow = (row & 1) ? (DEX + n0 + (row >> 1)) : (n0 + (row >> 1));
        } else {
            brow = n0 + row;
        }
        uint32_t db = smem_u32 + (uint32_t)(STG_S + stage) * TILE_S
                               + row * 128 + sw;
        const void* sb = (const void*)(gB + (size_t)brow * Ks
                                          + (size_t)kt * 64 + col * 8);
        asm volatile("cp.async.cg.shared.global [%0], [%1], 16;"
                     :: "r"(db), "l"(sb));
    }
}

template<int MODE>
__global__ __launch_bounds__(NTH_S, 2) void gemm_sq(
    const __half* __restrict__ A,  const __half* __restrict__ B,
    const __half* __restrict__ A2, const __half* __restrict__ B2,
    void* __restrict__ Cout, int N, int K, int Kt) {
    extern __shared__ char smem[];
    const uint32_t smem_u32 = (uint32_t)__cvta_generic_to_shared(smem);
    const int tid  = threadIdx.x;
    const int warp = tid >> 5, lane = tid & 31;
    const int wm = warp >> 1, wn = warp & 1;   // 2x2 warps of 64x64
    const int gid = lane >> 2, tig = lane & 3;

    // grouped CTA swizzle (8 y-tiles per x step) for L2 reuse of B panels
    int bx = blockIdx.x, by = blockIdx.y;
    if (gridDim.x > 1) {
        const int GRP = 8;
        int lin = by * gridDim.x + bx;
        int per = gridDim.x * GRP;
        int g   = lin / per, rem = lin % per;
        int gy  = g * GRP;
        int h   = gridDim.y - gy; if (h > GRP) h = GRP;
        by = gy + rem % h;
        bx = rem / h;
    }
    const int m0 = by * BMS;
    const int n0 = bx * ((MODE == 1) ? 64 : BNS);

    float acc[4][8][4];
#pragma unroll
    for (int a = 0; a < 4; a++)
#pragma unroll
        for (int b = 0; b < 8; b++)
#pragma unroll
            for (int c = 0; c < 4; c++) acc[a][b][c] = 0.0f;

    const int a_row_in = (lane & 15);
    const int a_ch_in  = (lane >> 4);
    const int b_row_in = ((lane >> 4) << 3) + (lane & 7);
    const int b_ch_in  = ((lane >> 3) & 1);

    for (int seg = 0; seg < 2; seg++) {
        const __half* gA = seg ? A2 : A;
        const __half* gB = seg ? B2 : B;
        const int Ks = seg ? Kt : K;
        if (Ks == 0) break;
        const int ktiles = Ks / 64;

        for (int p = 0; p < STG_S - 1; p++) {
            if (p < ktiles)
                load_tiles_s<MODE>(smem_u32, p, gA, gB, m0, n0, Ks, p, tid);
            asm volatile("cp.async.commit_group;");
        }

        for (int kt = 0; kt < ktiles; kt++) {
            asm volatile("cp.async.wait_group %0;" :: "n"(STG_S - 2));
            __syncthreads();

            const int st = kt % STG_S;
            const uint32_t sA = smem_u32 + (uint32_t)st * TILE_S;
            const uint32_t sB = smem_u32 + (uint32_t)(STG_S + st) * TILE_S;

            uint32_t ra[4][4], rb[8][2];
            auto frags = [&](int kk) {
#pragma unroll
                for (int mi = 0; mi < 4; mi++) {
                    int row = wm * 64 + mi * 16 + a_row_in;
                    int ch  = (kk >> 3) + a_ch_in;
                    uint32_t ad = sA + row * 128 + ((uint32_t)(ch ^ (row & 7)) << 4);
                    asm volatile(
                        "ldmatrix.sync.aligned.m8n8.x4.shared.b16 {%0,%1,%2,%3}, [%4];"
                        : "=r"(ra[mi][0]), "=r"(ra[mi][1]),
                          "=r"(ra[mi][2]), "=r"(ra[mi][3])
                        : "r"(ad));
                }
#pragma unroll
                for (int p = 0; p < 4; p++) {
                    int row = wn * 64 + p * 16 + b_row_in;
                    int ch  = (kk >> 3) + b_ch_in;
                    uint32_t bd = sB + row * 128 + ((uint32_t)(ch ^ (row & 7)) << 4);
                    asm volatile(
                        "ldmatrix.sync.aligned.m8n8.x4.shared.b16 {%0,%1,%2,%3}, [%4];"
                        : "=r"(rb[2*p][0]), "=r"(rb[2*p][1]),
                          "=r"(rb[2*p+1][0]), "=r"(rb[2*p+1][1])
                        : "r"(bd));
                }
            };
            auto mmas = [&]() {
#pragma unroll
                for (int mi = 0; mi < 4; mi++)
#pragma unroll
                    for (int ni = 0; ni < 8; ni++)
                        asm volatile(
                            "mma.sync.aligned.m16n8k16.row.col.f32.f16.f16.f32 "
                            "{%0,%1,%2,%3}, {%4,%5,%6,%7}, {%8,%9}, {%0,%1,%2,%3};"
                            : "+f"(acc[mi][ni][0]), "+f"(acc[mi][ni][1]),
                              "+f"(acc[mi][ni][2]), "+f"(acc[mi][ni][3])
                            : "r"(ra[mi][0]), "r"(ra[mi][1]),
                              "r"(ra[mi][2]), "r"(ra[mi][3]),
                              "r"(rb[ni][0]), "r"(rb[ni][1]));
            };

            frags(0);
            mmas();
            int nk = kt + STG_S - 1;
            if (nk < ktiles)
                load_tiles_s<MODE>(smem_u32, nk % STG_S, gA, gB, m0, n0, Ks,
                                   nk, tid);
            asm volatile("cp.async.commit_group;");
#pragma unroll
            for (int kk = 16; kk < 64; kk += 16) { frags(kk); mmas(); }
        }
        asm volatile("cp.async.wait_group 0;");
        __syncthreads();
    }

    if (MODE == 0) {
        float* C = (float*)Cout;
#pragma unroll
        for (int mi = 0; mi < 4; mi++) {
            int r0 = m0 + wm * 64 + mi * 16 + gid;
#pragma unroll
            for (int ni = 0; ni < 8; ni++) {
                int c0 = n0 + wn * 64 + ni * 8 + tig * 2;
                float2 v0 = make_float2(acc[mi][ni][0] * INV_GEMM,
                                        acc[mi][ni][1] * INV_GEMM);
                float2 v1 = make_float2(acc[mi][ni][2] * INV_GEMM,
                                        acc[mi][ni][3] * INV_GEMM);
                *reinterpret_cast<float2*>(C + (size_t)r0 * N + c0) = v0;
                *reinterpret_cast<float2*>(C + (size_t)(r0 + 8) * N + c0) = v1;
            }
        }
    } else {
        // MODE 1: acc pair (c0,c1) = (gate,up) raw; local d = wn*32+ni*4+tig
        float* hs = reinterpret_cast<float*>(smem);   // [128][68] padded
#pragma unroll
        for (int mi = 0; mi < 4; mi++) {
            int rl = wm * 64 + mi * 16 + gid;
#pragma unroll
            for (int ni = 0; ni < 8; ni++) {
                int dl = wn * 32 + ni * 4 + tig;      // 0..63
                float g0 = acc[mi][ni][0] * INV_GEMM, u0 = acc[mi][ni][1] * INV_GEMM;
                hs[rl * 68 + dl]       = u0 * g0 / (1.0f + __expf(-g0));
                float g1 = acc[mi][ni][2] * INV_GEMM, u1 = acc[mi][ni][3] * INV_GEMM;
                hs[(rl + 8) * 68 + dl] = u1 * g1 / (1.0f + __expf(-g1));
            }
        }
        __syncthreads();
        __half* He = (__half*)Cout;
#pragma unroll
        for (int it = 0; it < 8; it++) {
            int rl  = it * 16 + (tid >> 3);
            int blk = tid & 7;
            float4 v0 = *reinterpret_cast<float4*>(&hs[rl * 68 + blk * 8]);
            float4 v1 = *reinterpret_cast<float4*>(&hs[rl * 68 + blk * 8 + 4]);
            float x[8] = {v0.x, v0.y, v0.z, v0.w, v1.x, v1.y, v1.z, v1.w};
            __half ob[8];
#pragma unroll
            for (int k = 0; k < 8; k++)
                ob[k] = __float2half_rn(x[k] * 16.0f);    // A-side scale
            *reinterpret_cast<uint4*>(
                He + (size_t)(m0 + rl) * K2P + (n0 + blk * 8)) =
                *reinterpret_cast<const uint4*>(ob);
        }
    }
}

// ============================================================================
// LoRA splitK kernel (proven 128x128, 8 warps 64x32, 256 thr): raw partials.
// ============================================================================
#define BM 128
#define STAGES 3
#define NTH 256
#define TILE_BYTES (BM * 64 * 2)               // 16 KB
#define SMEM_BYTES (2 * STAGES * TILE_BYTES)   // 96 KB

__device__ __forceinline__ void load_tiles_l(uint32_t smem_u32, int stage,
                                             const __half* gA,
                                             const __half* gB,
                                             int m0, int Ks, int kt, int tid) {
#pragma unroll
    for (int i = 0; i < 4; i++) {
        int c = tid + i * NTH;
        int row = c >> 3;
        int col = c & 7;
        uint32_t sw = (uint32_t)(col ^ (row & 7)) << 4;
        uint32_t da = smem_u32 + (uint32_t)stage * TILE_BYTES + row * 128 + sw;
        const void* sa = (const void*)(gA + (size_t)(m0 + row) * Ks
                                          + (size_t)kt * 64 + col * 8);
        asm volatile("cp.async.cg.shared.global [%0], [%1], 16;"
                     :: "r"(da), "l"(sa));
        int brow = row < RK ? row : RK - 1;     // clamp (N=64)
        uint32_t db = smem_u32 + (uint32_t)(STAGES + stage) * TILE_BYTES
                               + row * 128 + sw;
        const void* sb = (const void*)(gB + (size_t)brow * Ks
                                          + (size_t)kt * 64 + col * 8);
        asm volatile("cp.async.cg.shared.global [%0], [%1], 16;"
                     :: "r"(db), "l"(sb));
    }
}

__global__ __launch_bounds__(NTH, 2) void gemm_lora(
    const __half* __restrict__ A, const __half* __restrict__ B,
    float* __restrict__ Cout, int K) {
    extern __shared__ char smem[];
    const uint32_t smem_u32 = (uint32_t)__cvta_generic_to_shared(smem);
    const int tid  = threadIdx.x;
    const int warp = tid >> 5, lane = tid & 31;
    const int wm = warp >> 2, wn = warp & 3;
    const int gid = lane >> 2, tig = lane & 3;
    const int m0 = blockIdx.y * BM;

    float acc[4][4][4];
#pragma unroll
    for (int a = 0; a < 4; a++)
#pragma unroll
        for (int b = 0; b < 4; b++)
#pragma unroll
            for (int c = 0; c < 4; c++) acc[a][b][c] = 0.0f;

    const int a_row_in = (lane & 15);
    const int a_ch_in  = (lane >> 4);
    const int b_row_in = ((lane >> 4) << 3) + (lane & 7);
    const int b_ch_in  = ((lane >> 3) & 1);

    const int cps  = (K / 64) / SPLITK;
    const int koff = blockIdx.z * cps;

    for (int p = 0; p < STAGES - 1; p++) {
        if (p < cps)
            load_tiles_l(smem_u32, p, A, B, m0, K, koff + p, tid);
        asm volatile("cp.async.commit_group;");
    }
    for (int kt = 0; kt < cps; kt++) {
        asm volatile("cp.async.wait_group %0;" :: "n"(STAGES - 2));
        __syncthreads();
        int nk = kt + STAGES - 1;
        if (nk < cps)
            load_tiles_l(smem_u32, nk % STAGES, A, B, m0, K, koff + nk, tid);
        asm volatile("cp.async.commit_group;");

        const int st = kt % STAGES;
        const uint32_t sA = smem_u32 + (uint32_t)st * TILE_BYTES;
        const uint32_t sB = smem_u32 + (uint32_t)(STAGES + st) * TILE_BYTES;
#pragma unroll
        for (int kk = 0; kk < 64; kk += 16) {
            uint32_t ra[4][4], rb[4][2];
#pragma unroll
            for (int mi = 0; mi < 4; mi++) {
                int row = wm * 64 + mi * 16 + a_row_in;
                int ch  = (kk >> 3) + a_ch_in;
                uint32_t ad = sA + row * 128 + ((uint32_t)(ch ^ (row & 7)) << 4);
                asm volatile(
                    "ldmatrix.sync.aligned.m8n8.x4.shared.b16 {%0,%1,%2,%3}, [%4];"
                    : "=r"(ra[mi][0]), "=r"(ra[mi][1]),
                      "=r"(ra[mi][2]), "=r"(ra[mi][3])
                    : "r"(ad));
            }
#pragma unroll
            for (int p = 0; p < 2; p++) {
                int row = wn * 32 + p * 16 + b_row_in;
                int ch  = (kk >> 3) + b_ch_in;
                uint32_t bd = sB + row * 128 + ((uint32_t)(ch ^ (row & 7)) << 4);
                asm volatile(
                    "ldmatrix.sync.aligned.m8n8.x4.shared.b16 {%0,%1,%2,%3}, [%4];"
                    : "=r"(rb[2*p][0]), "=r"(rb[2*p][1]),
                      "=r"(rb[2*p+1][0]), "=r"(rb[2*p+1][1])
                    : "r"(bd));
            }
#pragma unroll
            for (int mi = 0; mi < 4; mi++)
#pragma unroll
                for (int ni = 0; ni < 4; ni++)
                    asm volatile(
                        "mma.sync.aligned.m16n8k16.row.col.f32.f16.f16.f32 "
                        "{%0,%1,%2,%3}, {%4,%5,%6,%7}, {%8,%9}, {%0,%1,%2,%3};"
                        : "+f"(acc[mi][ni][0]), "+f"(acc[mi][ni][1]),
                          "+f"(acc[mi][ni][2]), "+f"(acc[mi][ni][3])
                        : "r"(ra[mi][0]), "r"(ra[mi][1]),
                          "r"(ra[mi][2]), "r"(ra[mi][3]),
                          "r"(rb[ni][0]), "r"(rb[ni][1]));
        }
    }
    asm volatile("cp.async.wait_group 0;");
    __syncthreads();

    float* C = Cout + (size_t)blockIdx.z * MTOK * RK;
#pragma unroll
    for (int mi = 0; mi < 4; mi++) {
        int r0 = m0 + wm * 64 + mi * 16 + gid;
#pragma unroll
        for (int ni = 0; ni < 4; ni++) {
            int c0 = wn * 32 + ni * 8 + tig * 2;
            if (c0 < RK) {
                float2 v0 = make_float2(acc[mi][ni][0], acc[mi][ni][1]);
                float2 v1 = make_float2(acc[mi][ni][2], acc[mi][ni][3]);
                *reinterpret_cast<float2*>(C + (size_t)r0 * RK + c0) = v0;
                *reinterpret_cast<float2*>(C + (size_t)(r0 + 8) * RK + c0) = v1;
            }
        }
    }
}

// ---------------- launcher ---------------------------------------------------
extern "C" void kernel_launch(void* const* d_in, const int* in_sizes, int n_in,
                              void* d_out, int out_size) {
    const float* X   = (const float*)d_in[0];
    const float* Wgu = (const float*)d_in[1];
    const float* Agu = (const float*)d_in[2];
    const float* Bgu = (const float*)d_in[3];
    const float* Wd  = (const float*)d_in[4];
    const float* Ad  = (const float*)d_in[5];
    const float* Bd  = (const float*)d_in[6];
    float* out = (float*)d_out;

    __half *Xe, *Wgue, *Ague, *Bgue, *Wde, *Ade, *Bde, *T1e, *T2e, *He;
    float *Pk;
    cudaGetSymbolAddress((void**)&Xe,   g_Xe);
    cudaGetSymbolAddress((void**)&Wgue, g_Wgue);
    cudaGetSymbolAddress((void**)&Ague, g_Ague);
    cudaGetSymbolAddress((void**)&Bgue, g_Bgue);
    cudaGetSymbolAddress((void**)&Wde,  g_Wde);
    cudaGetSymbolAddress((void**)&Ade,  g_Ade);
    cudaGetSymbolAddress((void**)&Bde,  g_Bde);
    cudaGetSymbolAddress((void**)&Pk,   g_Pk);
    cudaGetSymbolAddress((void**)&T1e,  g_T1e);
    cudaGetSymbolAddress((void**)&T2e,  g_T2e);
    cudaGetSymbolAddress((void**)&He,   g_He);

    cudaFuncSetAttribute(gemm_sq<0>,
                         cudaFuncAttributeMaxDynamicSharedMemorySize, SMEM_S);
    cudaFuncSetAttribute(gemm_sq<1>,
                         cudaFuncAttributeMaxDynamicSharedMemorySize, SMEM_S);
    cudaFuncSetAttribute(gemm_lora,
                         cudaFuncAttributeMaxDynamicSharedMemorySize, SMEM_BYTES);

    const int T = 256;
    auto g8 = [&](size_t n) { return (unsigned)((n / 8 + T - 1) / T); };

    // big operands plain fp16: A-side scale 16, B-side scale 64
    { size_t n = (size_t)MTOK * HID;
      cvt_plain8<<<g8(n), T>>>(X, Xe, n/8, 16.0f); }
    { size_t n = (size_t)2 * DEX * HID;
      cvt_plain8<<<g8(n), T>>>(Wgu, Wgue, n/8, 64.0f); }
    { size_t n = (size_t)RK * HID;
      cvt_plain8<<<g8(n), T>>>(Agu, Ague, n/8, 64.0f); }
    { size_t n = (size_t)HID * DEX;
      cvt_plain8<<<g8(n), T>>>(Wd, Wde, n/8, 64.0f); }
    { size_t n = (size_t)RK * DEX;
      cvt_plain8<<<g8(n), T>>>(Ad, Ade, n/8, 64.0f); }
    // LoRA B tails keep split-pair expansion (B-dup form)
    { size_t n = (size_t)2 * DEX * RK;
      cvt_expand8<false><<<g8(n), T>>>(Bgu, Bgue, n/8, 64.0f); }
    { size_t n = (size_t)HID * RK;
      cvt_expand8<false><<<g8(n), T>>>(Bd, Bde, n/8, 64.0f); }

    const unsigned gr = (unsigned)(((size_t)MTOK * RK + T - 1) / T);

    // T1 raw = 1024*(X @ Agu^T), splitK x4 -> reduce(/256) -> T1e pairs
    gemm_lora<<<dim3(1, MTOK/BM, SPLITK), NTH, SMEM_BYTES>>>(Xe, Ague, Pk, K1P);
    reduce_expand<<<gr, T>>>(Pk, T1e);

    // He = 16*swiglu(X@Wgu^T + 0.25*T1@Bgu^T), plain fp16 (square 64x64 warps)
    gemm_sq<1><<<dim3(DEX/64, MTOK/BMS), NTH_S, SMEM_S>>>(
        Xe, Wgue, T1e, Bgue, He, 2*DEX, K1P, KRE);

    // T2 raw = 1024*(H @ Ad^T), splitK x4 -> reduce -> T2e
    gemm_lora<<<dim3(1, MTOK/BM, SPLITK), NTH, SMEM_BYTES>>>(He, Ade, Pk, K2P);
    reduce_expand<<<gr, T>>>(Pk, T2e);

    // out = H@Wd^T + 0.25*T2@Bd^T (square 64x64 warps)
    gemm_sq<0><<<dim3(HID/BNS, MTOK/BMS), NTH_S, SMEM_S>>>(
        He, Wde, T2e, Bde, out, HID, K2P, KRE);
}

// round 13
// speedup vs baseline: 1.1374x; 1.0100x over previous
#include <cuda_runtime.h>
#include <cuda_fp16.h>
#include <cstdint>

#define MTOK 8192
#define HID  2048
#define DEX  4096
#define RK   64
#define K1P  HID       // 2048  GEMM1 K (plain fp16 both sides)
#define K2P  DEX       // 4096  GEMM2 K (plain fp16 both sides)
#define KRE  (2*RK)    // 128   LoRA tail K (split pairs)
#define SPLITK 4
// scaling: A-side stored = 16*true, B-side = 64*true, GEMM raw = 1024*true
#define INV_GEMM (1.0f/1024.0f)

// ---------------- scratch (device globals) ----------------------------------
__device__ __align__(16) __half g_Xe  [(size_t)MTOK * K1P];
__device__ __align__(16) __half g_Wgue[(size_t)2*DEX * K1P];
__device__ __align__(16) __half g_Ague[(size_t)RK * K1P];
__device__ __align__(16) __half g_Bgue[(size_t)2*DEX * KRE];
__device__ __align__(16) __half g_Wde [(size_t)HID * K2P];
__device__ __align__(16) __half g_Ade [(size_t)RK * K2P];
__device__ __align__(16) __half g_Bde [(size_t)HID * KRE];
__device__ __align__(16) float  g_Pk  [(size_t)SPLITK * MTOK * RK];
__device__ __align__(16) __half g_T1e [(size_t)MTOK * KRE];
__device__ __align__(16) __half g_T2e [(size_t)MTOK * KRE];
__device__ __align__(16) __half g_He  [(size_t)MTOK * K2P];

// ---------------- fp32 -> fp16 split pair (B-dup) for LoRA tails ------------
template<bool ASIDE>
__global__ void cvt_expand8(const float* __restrict__ in,
                            __half* __restrict__ out,
                            size_t n8, float scale) {
    size_t i = (size_t)blockIdx.x * blockDim.x + threadIdx.x;
    if (i >= n8) return;
    const float4* p = reinterpret_cast<const float4*>(in) + i * 2;
    float4 v0 = p[0], v1 = p[1];
    float x[8] = {v0.x, v0.y, v0.z, v0.w, v1.x, v1.y, v1.z, v1.w};
    __half ob[16];
#pragma unroll
    for (int k = 0; k < 8; k++) {
        float xv = x[k] * scale;
        __half hi = __float2half_rn(xv);
        ob[2*k] = hi;
        if (ASIDE) ob[2*k+1] = __float2half_rn(xv - __half2float(hi));
        else       ob[2*k+1] = hi;
    }
    uint4* o = reinterpret_cast<uint4*>(out + i * 16);
    const uint4* s = reinterpret_cast<const uint4*>(ob);
    o[0] = s[0]; o[1] = s[1];
}

// ---------------- fp32 -> plain fp16 (16 elems/thread, high MLP) ------------
__global__ void cvt_plain16(const float* __restrict__ in,
                            __half* __restrict__ out,
                            size_t n16, float scale) {
    size_t i = (size_t)blockIdx.x * blockDim.x + threadIdx.x;
    if (i >= n16) return;
    const float4* p = reinterpret_cast<const float4*>(in) + i * 4;
    float4 v0 = p[0], v1 = p[1], v2 = p[2], v3 = p[3];
    float x[16] = {v0.x,v0.y,v0.z,v0.w, v1.x,v1.y,v1.z,v1.w,
                   v2.x,v2.y,v2.z,v2.w, v3.x,v3.y,v3.z,v3.w};
    __half ob[16];
#pragma unroll
    for (int k = 0; k < 16; k++) ob[k] = __float2half_rn(x[k] * scale);
    uint4* o = reinterpret_cast<uint4*>(out + i * 16);
    const uint4* s = reinterpret_cast<const uint4*>(ob);
    o[0] = s[0]; o[1] = s[1];
}

// ---------------- splitK reduce + scale + A-side fp16 pair ------------------
__global__ void reduce_expand(const float* __restrict__ P,
                              __half* __restrict__ out) {
    size_t idx = (size_t)blockIdx.x * blockDim.x + threadIdx.x;
    if (idx >= (size_t)MTOK * RK) return;
    const size_t S = (size_t)MTOK * RK;
    float s = (P[idx] + P[idx + S] + P[idx + 2*S] + P[idx + 3*S]) * (1.0f/256.0f);
    __half hi = __float2half_rn(s);
    out[2*idx]   = hi;
    out[2*idx+1] = __float2half_rn(s - __half2float(hi));
}

// ============================================================================
// SQ kernel: CTA 128x128, 4 warps (2x2) of 64x64, 128 threads, 2 CTAs/SM,
// double-buffered fragments.  MODE 0: C fp32 (descaled) + LoRA tail.
// MODE 1: fused SwiGLU -> He plain fp16 (x16), gate/up interleaved B rows.
// ============================================================================
#define BMS 128
#define BNS 128
#define STG_S 3
#define NTH_S 128
#define TILE_S (128 * 64 * 2)                  // 16 KB
#define SMEM_S (2 * STG_S * TILE_S)            // 96 KB

template<int MODE>
__device__ __forceinline__ void load_tiles_s(uint32_t smem_u32, int stage,
                                             const __half* gA,
                                             const __half* gB,
                                             int m0, int n0, int Ks,
                                             int kt, int tid) {
#pragma unroll
    for (int i = 0; i < 8; i++) {
        int c = tid + i * NTH_S;        // 0..1023 16B chunks per operand
        int row = c >> 3;
        int col = c & 7;
        uint32_t sw = (uint32_t)(col ^ (row & 7)) << 4;
        uint32_t da = smem_u32 + (uint32_t)stage * TILE_S + row * 128 + sw;
        const void* sa = (const void*)(gA + (size_t)(m0 + row) * Ks
                                          + (size_t)kt * 64 + col * 8);
        asm volatile("cp.async.cg.shared.global [%0], [%1], 16;"
                     :: "r"(da), "l"(sa));
        int brow;
        if (MODE == 1) {                // gate/up interleave; n0 = d-offset
            brow = (row & 1) ? (DEX + n0 + (row >> 1)) : (n0 + (row >> 1));
        } else {
            brow = n0 + row;
        }
        uint32_t db = smem_u32 + (uint32_t)(STG_S + stage) * TILE_S
                               + row * 128 + sw;
        const void* sb = (const void*)(gB + (size_t)brow * Ks
                                          + (size_t)kt * 64 + col * 8);
        asm volatile("cp.async.cg.shared.global [%0], [%1], 16;"
                     :: "r"(db), "l"(sb));
    }
}

template<int MODE>
__global__ __launch_bounds__(NTH_S, 2) void gemm_sq(
    const __half* __restrict__ A,  const __half* __restrict__ B,
    const __half* __restrict__ A2, const __half* __restrict__ B2,
    void* __restrict__ Cout, int N, int K, int Kt) {
    extern __shared__ char smem[];
    const uint32_t smem_u32 = (uint32_t)__cvta_generic_to_shared(smem);
    const int tid  = threadIdx.x;
    const int warp = tid >> 5, lane = tid & 31;
    const int wm = warp >> 1, wn = warp & 1;   // 2x2 warps of 64x64
    const int gid = lane >> 2, tig = lane & 3;

    // grouped CTA swizzle (8 y-tiles per x step) for L2 reuse of B panels
    int bx = blockIdx.x, by = blockIdx.y;
    if (gridDim.x > 1) {
        const int GRP = 8;
        int lin = by * gridDim.x + bx;
        int per = gridDim.x * GRP;
        int g   = lin / per, rem = lin % per;
        int gy  = g * GRP;
        int h   = gridDim.y - gy; if (h > GRP) h = GRP;
        by = gy + rem % h;
        bx = rem / h;
    }
    const int m0 = by * BMS;
    const int n0 = bx * ((MODE == 1) ? 64 : BNS);

    float acc[4][8][4];
#pragma unroll
    for (int a = 0; a < 4; a++)
#pragma unroll
        for (int b = 0; b < 8; b++)
#pragma unroll
            for (int c = 0; c < 4; c++) acc[a][b][c] = 0.0f;

    const int a_row_in = (lane & 15);
    const int a_ch_in  = (lane >> 4);
    const int b_row_in = ((lane >> 4) << 3) + (lane & 7);
    const int b_ch_in  = ((lane >> 3) & 1);

    for (int seg = 0; seg < 2; seg++) {
        const __half* gA = seg ? A2 : A;
        const __half* gB = seg ? B2 : B;
        const int Ks = seg ? Kt : K;
        if (Ks == 0) break;
        const int ktiles = Ks / 64;

        for (int p = 0; p < STG_S - 1; p++) {
            if (p < ktiles)
                load_tiles_s<MODE>(smem_u32, p, gA, gB, m0, n0, Ks, p, tid);
            asm volatile("cp.async.commit_group;");
        }

        for (int kt = 0; kt < ktiles; kt++) {
            asm volatile("cp.async.wait_group %0;" :: "n"(STG_S - 2));
            __syncthreads();

            const int st = kt % STG_S;
            const uint32_t sA = smem_u32 + (uint32_t)st * TILE_S;
            const uint32_t sB = smem_u32 + (uint32_t)(STG_S + st) * TILE_S;

            // double-buffered fragments (reg budget: 128 acc + 64 frag < 256)
            uint32_t ra[2][4][4], rb[2][8][2];
            auto frags = [&](int kk, int buf) {
#pragma unroll
                for (int mi = 0; mi < 4; mi++) {
                    int row = wm * 64 + mi * 16 + a_row_in;
                    int ch  = (kk >> 3) + a_ch_in;
                    uint32_t ad = sA + row * 128 + ((uint32_t)(ch ^ (row & 7)) << 4);
                    asm volatile(
                        "ldmatrix.sync.aligned.m8n8.x4.shared.b16 {%0,%1,%2,%3}, [%4];"
                        : "=r"(ra[buf][mi][0]), "=r"(ra[buf][mi][1]),
                          "=r"(ra[buf][mi][2]), "=r"(ra[buf][mi][3])
                        : "r"(ad));
                }
#pragma unroll
                for (int p = 0; p < 4; p++) {
                    int row = wn * 64 + p * 16 + b_row_in;
                    int ch  = (kk >> 3) + b_ch_in;
                    uint32_t bd = sB + row * 128 + ((uint32_t)(ch ^ (row & 7)) << 4);
                    asm volatile(
                        "ldmatrix.sync.aligned.m8n8.x4.shared.b16 {%0,%1,%2,%3}, [%4];"
                        : "=r"(rb[buf][2*p][0]), "=r"(rb[buf][2*p][1]),
                          "=r"(rb[buf][2*p+1][0]), "=r"(rb[buf][2*p+1][1])
                        : "r"(bd));
                }
            };
            auto mmas = [&](int buf) {
#pragma unroll
                for (int mi = 0; mi < 4; mi++)
#pragma unroll
                    for (int ni = 0; ni < 8; ni++)
                        asm volatile(
                            "mma.sync.aligned.m16n8k16.row.col.f32.f16.f16.f32 "
                            "{%0,%1,%2,%3}, {%4,%5,%6,%7}, {%8,%9}, {%0,%1,%2,%3};"
                            : "+f"(acc[mi][ni][0]), "+f"(acc[mi][ni][1]),
                              "+f"(acc[mi][ni][2]), "+f"(acc[mi][ni][3])
                            : "r"(ra[buf][mi][0]), "r"(ra[buf][mi][1]),
                              "r"(ra[buf][mi][2]), "r"(ra[buf][mi][3]),
                              "r"(rb[buf][ni][0]), "r"(rb[buf][ni][1]));
            };

            // prefetch kk+1 while kk's MMAs issue; next-chunk loads after mmas(0)
            frags(0, 0);
            frags(16, 1);
            mmas(0);
            int nk = kt + STG_S - 1;
            if (nk < ktiles)
                load_tiles_s<MODE>(smem_u32, nk % STG_S, gA, gB, m0, n0, Ks,
                                   nk, tid);
            asm volatile("cp.async.commit_group;");
            frags(32, 0);
            mmas(1);
            frags(48, 1);
            mmas(0);
            mmas(1);
        }
        asm volatile("cp.async.wait_group 0;");
        __syncthreads();
    }

    if (MODE == 0) {
        float* C = (float*)Cout;
#pragma unroll
        for (int mi = 0; mi < 4; mi++) {
            int r0 = m0 + wm * 64 + mi * 16 + gid;
#pragma unroll
            for (int ni = 0; ni < 8; ni++) {
                int c0 = n0 + wn * 64 + ni * 8 + tig * 2;
                float2 v0 = make_float2(acc[mi][ni][0] * INV_GEMM,
                                        acc[mi][ni][1] * INV_GEMM);
                float2 v1 = make_float2(acc[mi][ni][2] * INV_GEMM,
                                        acc[mi][ni][3] * INV_GEMM);
                *reinterpret_cast<float2*>(C + (size_t)r0 * N + c0) = v0;
                *reinterpret_cast<float2*>(C + (size_t)(r0 + 8) * N + c0) = v1;
            }
        }
    } else {
        // MODE 1: acc pair (c0,c1) = (gate,up) raw; local d = wn*32+ni*4+tig
        float* hs = reinterpret_cast<float*>(smem);   // [128][68] padded
#pragma unroll
        for (int mi = 0; mi < 4; mi++) {
            int rl = wm * 64 + mi * 16 + gid;
#pragma unroll
            for (int ni = 0; ni < 8; ni++) {
                int dl = wn * 32 + ni * 4 + tig;      // 0..63
                float g0 = acc[mi][ni][0] * INV_GEMM, u0 = acc[mi][ni][1] * INV_GEMM;
                hs[rl * 68 + dl]       = u0 * g0 / (1.0f + __expf(-g0));
                float g1 = acc[mi][ni][2] * INV_GEMM, u1 = acc[mi][ni][3] * INV_GEMM;
                hs[(rl + 8) * 68 + dl] = u1 * g1 / (1.0f + __expf(-g1));
            }
        }
        __syncthreads();
        __half* He = (__half*)Cout;
#pragma unroll
        for (int it = 0; it < 8; it++) {
            int rl  = it * 16 + (tid >> 3);
            int blk = tid & 7;
            float4 v0 = *reinterpret_cast<float4*>(&hs[rl * 68 + blk * 8]);
            float4 v1 = *reinterpret_cast<float4*>(&hs[rl * 68 + blk * 8 + 4]);
            float x[8] = {v0.x, v0.y, v0.z, v0.w, v1.x, v1.y, v1.z, v1.w};
            __half ob[8];
#pragma unroll
            for (int k = 0; k < 8; k++)
                ob[k] = __float2half_rn(x[k] * 16.0f);    // A-side scale
            *reinterpret_cast<uint4*>(
                He + (size_t)(m0 + rl) * K2P + (n0 + blk * 8)) =
                *reinterpret_cast<const uint4*>(ob);
        }
    }
}

// ============================================================================
// LoRA splitK kernel (proven 128x128, 8 warps 64x32, 256 thr): raw partials.
// ============================================================================
#define BM 128
#define STAGES 3
#define NTH 256
#define TILE_BYTES (BM * 64 * 2)               // 16 KB
#define SMEM_BYTES (2 * STAGES * TILE_BYTES)   // 96 KB

__device__ __forceinline__ void load_tiles_l(uint32_t smem_u32, int stage,
                                             const __half* gA,
                                             const __half* gB,
                                             int m0, int Ks, int kt, int tid) {
#pragma unroll
    for (int i = 0; i < 4; i++) {
        int c = tid + i * NTH;
        int row = c >> 3;
        int col = c & 7;
        uint32_t sw = (uint32_t)(col ^ (row & 7)) << 4;
        uint32_t da = smem_u32 + (uint32_t)stage * TILE_BYTES + row * 128 + sw;
        const void* sa = (const void*)(gA + (size_t)(m0 + row) * Ks
                                          + (size_t)kt * 64 + col * 8);
        asm volatile("cp.async.cg.shared.global [%0], [%1], 16;"
                     :: "r"(da), "l"(sa));
        int brow = row < RK ? row : RK - 1;     // clamp (N=64)
        uint32_t db = smem_u32 + (uint32_t)(STAGES + stage) * TILE_BYTES
                               + row * 128 + sw;
        const void* sb = (const void*)(gB + (size_t)brow * Ks
                                          + (size_t)kt * 64 + col * 8);
        asm volatile("cp.async.cg.shared.global [%0], [%1], 16;"
                     :: "r"(db), "l"(sb));
    }
}

__global__ __launch_bounds__(NTH, 2) void gemm_lora(
    const __half* __restrict__ A, const __half* __restrict__ B,
    float* __restrict__ Cout, int K) {
    extern __shared__ char smem[];
    const uint32_t smem_u32 = (uint32_t)__cvta_generic_to_shared(smem);
    const int tid  = threadIdx.x;
    const int warp = tid >> 5, lane = tid & 31;
    const int wm = warp >> 2, wn = warp & 3;
    const int gid = lane >> 2, tig = lane & 3;
    const int m0 = blockIdx.y * BM;

    float acc[4][4][4];
#pragma unroll
    for (int a = 0; a < 4; a++)
#pragma unroll
        for (int b = 0; b < 4; b++)
#pragma unroll
            for (int c = 0; c < 4; c++) acc[a][b][c] = 0.0f;

    const int a_row_in = (lane & 15);
    const int a_ch_in  = (lane >> 4);
    const int b_row_in = ((lane >> 4) << 3) + (lane & 7);
    const int b_ch_in  = ((lane >> 3) & 1);

    const int cps  = (K / 64) / SPLITK;
    const int koff = blockIdx.z * cps;

    for (int p = 0; p < STAGES - 1; p++) {
        if (p < cps)
            load_tiles_l(smem_u32, p, A, B, m0, K, koff + p, tid);
        asm volatile("cp.async.commit_group;");
    }
    for (int kt = 0; kt < cps; kt++) {
        asm volatile("cp.async.wait_group %0;" :: "n"(STAGES - 2));
        __syncthreads();
        int nk = kt + STAGES - 1;
        if (nk < cps)
            load_tiles_l(smem_u32, nk % STAGES, A, B, m0, K, koff + nk, tid);
        asm volatile("cp.async.commit_group;");

        const int st = kt % STAGES;
        const uint32_t sA = smem_u32 + (uint32_t)st * TILE_BYTES;
        const uint32_t sB = smem_u32 + (uint32_t)(STAGES + st) * TILE_BYTES;
#pragma unroll
        for (int kk = 0; kk < 64; kk += 16) {
            uint32_t ra[4][4], rb[4][2];
#pragma unroll
            for (int mi = 0; mi < 4; mi++) {
                int row = wm * 64 + mi * 16 + a_row_in;
                int ch  = (kk >> 3) + a_ch_in;
                uint32_t ad = sA + row * 128 + ((uint32_t)(ch ^ (row & 7)) << 4);
                asm volatile(
                    "ldmatrix.sync.aligned.m8n8.x4.shared.b16 {%0,%1,%2,%3}, [%4];"
                    : "=r"(ra[mi][0]), "=r"(ra[mi][1]),
                      "=r"(ra[mi][2]), "=r"(ra[mi][3])
                    : "r"(ad));
            }
#pragma unroll
            for (int p = 0; p < 2; p++) {
                int row = wn * 32 + p * 16 + b_row_in;
                int ch  = (kk >> 3) + b_ch_in;
                uint32_t bd = sB + row * 128 + ((uint32_t)(ch ^ (row & 7)) << 4);
                asm volatile(
                    "ldmatrix.sync.aligned.m8n8.x4.shared.b16 {%0,%1,%2,%3}, [%4];"
                    : "=r"(rb[2*p][0]), "=r"(rb[2*p][1]),
                      "=r"(rb[2*p+1][0]), "=r"(rb[2*p+1][1])
                    : "r"(bd));
            }
#pragma unroll
            for (int mi = 0; mi < 4; mi++)
#pragma unroll
                for (int ni = 0; ni < 4; ni++)
                    asm volatile(
                        "mma.sync.aligned.m16n8k16.row.col.f32.f16.f16.f32 "
                        "{%0,%1,%2,%3}, {%4,%5,%6,%7}, {%8,%9}, {%0,%1,%2,%3};"
                        : "+f"(acc[mi][ni][0]), "+f"(acc[mi][ni][1]),
                          "+f"(acc[mi][ni][2]), "+f"(acc[mi][ni][3])
                        : "r"(ra[mi][0]), "r"(ra[mi][1]),
                          "r"(ra[mi][2]), "r"(ra[mi][3]),
                          "r"(rb[ni][0]), "r"(rb[ni][1]));
        }
    }
    asm volatile("cp.async.wait_group 0;");
    __syncthreads();

    float* C = Cout + (size_t)blockIdx.z * MTOK * RK;
#pragma unroll
    for (int mi = 0; mi < 4; mi++) {
        int r0 = m0 + wm * 64 + mi * 16 + gid;
#pragma unroll
        for (int ni = 0; ni < 4; ni++) {
            int c0 = wn * 32 + ni * 8 + tig * 2;
            if (c0 < RK) {
                float2 v0 = make_float2(acc[mi][ni][0], acc[mi][ni][1]);
                float2 v1 = make_float2(acc[mi][ni][2], acc[mi][ni][3]);
                *reinterpret_cast<float2*>(C + (size_t)r0 * RK + c0) = v0;
                *reinterpret_cast<float2*>(C + (size_t)(r0 + 8) * RK + c0) = v1;
            }
        }
    }
}

// ---------------- launcher ---------------------------------------------------
extern "C" void kernel_launch(void* const* d_in, const int* in_sizes, int n_in,
                              void* d_out, int out_size) {
    const float* X   = (const float*)d_in[0];
    const float* Wgu = (const float*)d_in[1];
    const float* Agu = (const float*)d_in[2];
    const float* Bgu = (const float*)d_in[3];
    const float* Wd  = (const float*)d_in[4];
    const float* Ad  = (const float*)d_in[5];
    const float* Bd  = (const float*)d_in[6];
    float* out = (float*)d_out;

    __half *Xe, *Wgue, *Ague, *Bgue, *Wde, *Ade, *Bde, *T1e, *T2e, *He;
    float *Pk;
    cudaGetSymbolAddress((void**)&Xe,   g_Xe);
    cudaGetSymbolAddress((void**)&Wgue, g_Wgue);
    cudaGetSymbolAddress((void**)&Ague, g_Ague);
    cudaGetSymbolAddress((void**)&Bgue, g_Bgue);
    cudaGetSymbolAddress((void**)&Wde,  g_Wde);
    cudaGetSymbolAddress((void**)&Ade,  g_Ade);
    cudaGetSymbolAddress((void**)&Bde,  g_Bde);
    cudaGetSymbolAddress((void**)&Pk,   g_Pk);
    cudaGetSymbolAddress((void**)&T1e,  g_T1e);
    cudaGetSymbolAddress((void**)&T2e,  g_T2e);
    cudaGetSymbolAddress((void**)&He,   g_He);

    cudaFuncSetAttribute(gemm_sq<0>,
                         cudaFuncAttributeMaxDynamicSharedMemorySize, SMEM_S);
    cudaFuncSetAttribute(gemm_sq<1>,
                         cudaFuncAttributeMaxDynamicSharedMemorySize, SMEM_S);
    cudaFuncSetAttribute(gemm_lora,
                         cudaFuncAttributeMaxDynamicSharedMemorySize, SMEM_BYTES);

    const int T = 256;
    auto g16 = [&](size_t n) { return (unsigned)((n / 16 + T - 1) / T); };
    auto g8  = [&](size_t n) { return (unsigned)((n / 8 + T - 1) / T); };

    // big operands plain fp16: A-side scale 16, B-side scale 64
    { size_t n = (size_t)MTOK * HID;
      cvt_plain16<<<g16(n), T>>>(X, Xe, n/16, 16.0f); }
    { size_t n = (size_t)2 * DEX * HID;
      cvt_plain16<<<g16(n), T>>>(Wgu, Wgue, n/16, 64.0f); }
    { size_t n = (size_t)RK * HID;
      cvt_plain16<<<g16(n), T>>>(Agu, Ague, n/16, 64.0f); }
    { size_t n = (size_t)HID * DEX;
      cvt_plain16<<<g16(n), T>>>(Wd, Wde, n/16, 64.0f); }
    { size_t n = (size_t)RK * DEX;
      cvt_plain16<<<g16(n), T>>>(Ad, Ade, n/16, 64.0f); }
    // LoRA B tails keep split-pair expansion (B-dup form)
    { size_t n = (size_t)2 * DEX * RK;
      cvt_expand8<false><<<g8(n), T>>>(Bgu, Bgue, n/8, 64.0f); }
    { size_t n = (size_t)HID * RK;
      cvt_expand8<false><<<g8(n), T>>>(Bd, Bde, n/8, 64.0f); }

    const unsigned gr = (unsigned)(((size_t)MTOK * RK + T - 1) / T);

    // T1 raw = 1024*(X @ Agu^T), splitK x4 -> reduce(/256) -> T1e pairs
    gemm_lora<<<dim3(1, MTOK/BM, SPLITK), NTH, SMEM_BYTES>>>(Xe, Ague, Pk, K1P);
    reduce_expand<<<gr, T>>>(Pk, T1e);

    // He = 16*swiglu(X@Wgu^T + 0.25*T1@Bgu^T), plain fp16 (square 64x64 warps)
    gemm_sq<1><<<dim3(DEX/64, MTOK/BMS), NTH_S, SMEM_S>>>(
        Xe, Wgue, T1e, Bgue, He, 2*DEX, K1P, KRE);

    // T2 raw = 1024*(H @ Ad^T), splitK x4 -> reduce -> T2e
    gemm_lora<<<dim3(1, MTOK/BM, SPLITK), NTH, SMEM_BYTES>>>(He, Ade, Pk, K2P);
    reduce_expand<<<gr, T>>>(Pk, T2e);

    // out = H@Wd^T + 0.25*T2@Bd^T (square 64x64 warps)
    gemm_sq<0><<<dim3(HID/BNS, MTOK/BMS), NTH_S, SMEM_S>>>(
        He, Wde, T2e, Bde, out, HID, K2P, KRE);
}

// round 14
// speedup vs baseline: 1.1452x; 1.0068x over previous
#include <cuda_runtime.h>
#include <cuda_fp16.h>
#include <cstdint>

#define MTOK 8192
#define HID  2048
#define DEX  4096
#define RK   64
#define K1P  HID       // 2048  GEMM1 K (plain fp16 both sides)
#define K2P  DEX       // 4096  GEMM2 K (plain fp16 both sides)
#define KRE  (2*RK)    // 128   LoRA tail K (split pairs)
#define SPLITK 4
// scaling: A-side stored = 16*true, B-side = 64*true, GEMM raw = 1024*true
#define INV_GEMM (1.0f/1024.0f)

// ---------------- scratch (device globals) ----------------------------------
__device__ __align__(16) __half g_Xe  [(size_t)MTOK * K1P];
__device__ __align__(16) __half g_Wgue[(size_t)2*DEX * K1P];
__device__ __align__(16) __half g_Ague[(size_t)RK * K1P];
__device__ __align__(16) __half g_Bgue[(size_t)2*DEX * KRE];
__device__ __align__(16) __half g_Wde [(size_t)HID * K2P];
__device__ __align__(16) __half g_Ade [(size_t)RK * K2P];
__device__ __align__(16) __half g_Bde [(size_t)HID * KRE];
__device__ __align__(16) float  g_Pk  [(size_t)SPLITK * MTOK * RK];
__device__ __align__(16) __half g_T1e [(size_t)MTOK * KRE];
__device__ __align__(16) __half g_T2e [(size_t)MTOK * KRE];
__device__ __align__(16) __half g_He  [(size_t)MTOK * K2P];

// ---------------- batched plain cvt: 5 segments in one launch ---------------
// 8 elems/thread (proven fastest form). Segment table passed by value.
struct CvtSeg { const float* in; __half* out; size_t n8; float scale; };
struct CvtTab5 { CvtSeg s[5]; size_t cum8[6]; };   // cum8[i] = start (in 8-elem units)

__global__ void cvt_plain_multi(CvtTab5 tab) {
    size_t i = (size_t)blockIdx.x * blockDim.x + threadIdx.x;
    if (i >= tab.cum8[5]) return;
    int sidx = 0;
#pragma unroll
    for (int k = 1; k < 5; k++) sidx += (i >= tab.cum8[k]) ? 1 : 0;
    const CvtSeg sg = tab.s[sidx];
    size_t j = i - tab.cum8[sidx];
    const float4* p = reinterpret_cast<const float4*>(sg.in) + j * 2;
    float4 v0 = p[0], v1 = p[1];
    float x[8] = {v0.x, v0.y, v0.z, v0.w, v1.x, v1.y, v1.z, v1.w};
    __half ob[8];
#pragma unroll
    for (int k = 0; k < 8; k++) ob[k] = __float2half_rn(x[k] * sg.scale);
    *reinterpret_cast<uint4*>(sg.out + j * 8) = *reinterpret_cast<const uint4*>(ob);
}

// ---------------- batched expand cvt: 2 segments (B-dup split pairs) --------
struct CvtTab2 { CvtSeg s[2]; size_t cum8[3]; };

__global__ void cvt_expand_multi(CvtTab2 tab) {
    size_t i = (size_t)blockIdx.x * blockDim.x + threadIdx.x;
    if (i >= tab.cum8[2]) return;
    int sidx = (i >= tab.cum8[1]) ? 1 : 0;
    const CvtSeg sg = tab.s[sidx];
    size_t j = i - tab.cum8[sidx];
    const float4* p = reinterpret_cast<const float4*>(sg.in) + j * 2;
    float4 v0 = p[0], v1 = p[1];
    float x[8] = {v0.x, v0.y, v0.z, v0.w, v1.x, v1.y, v1.z, v1.w};
    __half ob[16];
#pragma unroll
    for (int k = 0; k < 8; k++) {
        float xv = x[k] * sg.scale;
        __half hi = __float2half_rn(xv);
        ob[2*k]   = hi;
        ob[2*k+1] = hi;     // B-dup form
    }
    uint4* o = reinterpret_cast<uint4*>(sg.out + j * 16);
    const uint4* s = reinterpret_cast<const uint4*>(ob);
    o[0] = s[0]; o[1] = s[1];
}

// ---------------- splitK reduce + scale + A-side fp16 pair ------------------
__global__ void reduce_expand(const float* __restrict__ P,
                              __half* __restrict__ out) {
    size_t idx = (size_t)blockIdx.x * blockDim.x + threadIdx.x;
    if (idx >= (size_t)MTOK * RK) return;
    const size_t S = (size_t)MTOK * RK;
    float s = (P[idx] + P[idx + S] + P[idx + 2*S] + P[idx + 3*S]) * (1.0f/256.0f);
    __half hi = __float2half_rn(s);
    out[2*idx]   = hi;
    out[2*idx+1] = __float2half_rn(s - __half2float(hi));
}

// ============================================================================
// SQ kernel: CTA 128x128, 4 warps (2x2) of 64x64, 128 threads, 2 CTAs/SM,
// double-buffered fragments.  MODE 0: C fp32 (descaled) + LoRA tail.
// MODE 1: fused SwiGLU -> He plain fp16 (x16), gate/up interleaved B rows.
// ============================================================================
#define BMS 128
#define BNS 128
#define STG_S 3
#define NTH_S 128
#define TILE_S (128 * 64 * 2)                  // 16 KB
#define SMEM_S (2 * STG_S * TILE_S)            // 96 KB

template<int MODE>
__device__ __forceinline__ void load_tiles_s(uint32_t smem_u32, int stage,
                                             const __half* gA,
                                             const __half* gB,
                                             int m0, int n0, int Ks,
                                             int kt, int tid) {
#pragma unroll
    for (int i = 0; i < 8; i++) {
        int c = tid + i * NTH_S;        // 0..1023 16B chunks per operand
        int row = c >> 3;
        int col = c & 7;
        uint32_t sw = (uint32_t)(col ^ (row & 7)) << 4;
        uint32_t da = smem_u32 + (uint32_t)stage * TILE_S + row * 128 + sw;
        const void* sa = (const void*)(gA + (size_t)(m0 + row) * Ks
                                          + (size_t)kt * 64 + col * 8);
        asm volatile("cp.async.cg.shared.global [%0], [%1], 16;"
                     :: "r"(da), "l"(sa));
        int brow;
        if (MODE == 1) {                // gate/up interleave; n0 = d-offset
            brow = (row & 1) ? (DEX + n0 + (row >> 1)) : (n0 + (row >> 1));
        } else {
            brow = n0 + row;
        }
        uint32_t db = smem_u32 + (uint32_t)(STG_S + stage) * TILE_S
                               + row * 128 + sw;
        const void* sb = (const void*)(gB + (size_t)brow * Ks
                                          + (size_t)kt * 64 + col * 8);
        asm volatile("cp.async.cg.shared.global [%0], [%1], 16;"
                     :: "r"(db), "l"(sb));
    }
}

template<int MODE>
__global__ __launch_bounds__(NTH_S, 2) void gemm_sq(
    const __half* __restrict__ A,  const __half* __restrict__ B,
    const __half* __restrict__ A2, const __half* __restrict__ B2,
    void* __restrict__ Cout, int N, int K, int Kt) {
    extern __shared__ char smem[];
    const uint32_t smem_u32 = (uint32_t)__cvta_generic_to_shared(smem);
    const int tid  = threadIdx.x;
    const int warp = tid >> 5, lane = tid & 31;
    const int wm = warp >> 1, wn = warp & 1;   // 2x2 warps of 64x64
    const int gid = lane >> 2, tig = lane & 3;

    // grouped CTA swizzle (8 y-tiles per x step) for L2 reuse of B panels
    int bx = blockIdx.x, by = blockIdx.y;
    if (gridDim.x > 1) {
        const int GRP = 8;
        int lin = by * gridDim.x + bx;
        int per = gridDim.x * GRP;
        int g   = lin / per, rem = lin % per;
        int gy  = g * GRP;
        int h   = gridDim.y - gy; if (h > GRP) h = GRP;
        by = gy + rem % h;
        bx = rem / h;
    }
    const int m0 = by * BMS;
    const int n0 = bx * ((MODE == 1) ? 64 : BNS);

    float acc[4][8][4];
#pragma unroll
    for (int a = 0; a < 4; a++)
#pragma unroll
        for (int b = 0; b < 8; b++)
#pragma unroll
            for (int c = 0; c < 4; c++) acc[a][b][c] = 0.0f;

    const int a_row_in = (lane & 15);
    const int a_ch_in  = (lane >> 4);
    const int b_row_in = ((lane >> 4) << 3) + (lane & 7);
    const int b_ch_in  = ((lane >> 3) & 1);

    for (int seg = 0; seg < 2; seg++) {
        const __half* gA = seg ? A2 : A;
        const __half* gB = seg ? B2 : B;
        const int Ks = seg ? Kt : K;
        if (Ks == 0) break;
        const int ktiles = Ks / 64;

        for (int p = 0; p < STG_S - 1; p++) {
            if (p < ktiles)
                load_tiles_s<MODE>(smem_u32, p, gA, gB, m0, n0, Ks, p, tid);
            asm volatile("cp.async.commit_group;");
        }

        for (int kt = 0; kt < ktiles; kt++) {
            asm volatile("cp.async.wait_group %0;" :: "n"(STG_S - 2));
            __syncthreads();

            const int st = kt % STG_S;
            const uint32_t sA = smem_u32 + (uint32_t)st * TILE_S;
            const uint32_t sB = smem_u32 + (uint32_t)(STG_S + st) * TILE_S;

            uint32_t ra[2][4][4], rb[2][8][2];
            auto frags = [&](int kk, int buf) {
#pragma unroll
                for (int mi = 0; mi < 4; mi++) {
                    int row = wm * 64 + mi * 16 + a_row_in;
                    int ch  = (kk >> 3) + a_ch_in;
                    uint32_t ad = sA + row * 128 + ((uint32_t)(ch ^ (row & 7)) << 4);
                    asm volatile(
                        "ldmatrix.sync.aligned.m8n8.x4.shared.b16 {%0,%1,%2,%3}, [%4];"
                        : "=r"(ra[buf][mi][0]), "=r"(ra[buf][mi][1]),
                          "=r"(ra[buf][mi][2]), "=r"(ra[buf][mi][3])
                        : "r"(ad));
                }
#pragma unroll
                for (int p = 0; p < 4; p++) {
                    int row = wn * 64 + p * 16 + b_row_in;
                    int ch  = (kk >> 3) + b_ch_in;
                    uint32_t bd = sB + row * 128 + ((uint32_t)(ch ^ (row & 7)) << 4);
                    asm volatile(
                        "ldmatrix.sync.aligned.m8n8.x4.shared.b16 {%0,%1,%2,%3}, [%4];"
                        : "=r"(rb[buf][2*p][0]), "=r"(rb[buf][2*p][1]),
                          "=r"(rb[buf][2*p+1][0]), "=r"(rb[buf][2*p+1][1])
                        : "r"(bd));
                }
            };
            auto mmas = [&](int buf) {
#pragma unroll
                for (int mi = 0; mi < 4; mi++)
#pragma unroll
                    for (int ni = 0; ni < 8; ni++)
                        asm volatile(
                            "mma.sync.aligned.m16n8k16.row.col.f32.f16.f16.f32 "
                            "{%0,%1,%2,%3}, {%4,%5,%6,%7}, {%8,%9}, {%0,%1,%2,%3};"
                            : "+f"(acc[mi][ni][0]), "+f"(acc[mi][ni][1]),
                              "+f"(acc[mi][ni][2]), "+f"(acc[mi][ni][3])
                            : "r"(ra[buf][mi][0]), "r"(ra[buf][mi][1]),
                              "r"(ra[buf][mi][2]), "r"(ra[buf][mi][3]),
                              "r"(rb[buf][ni][0]), "r"(rb[buf][ni][1]));
            };

            frags(0, 0);
            frags(16, 1);
            mmas(0);
            int nk = kt + STG_S - 1;
            if (nk < ktiles)
                load_tiles_s<MODE>(smem_u32, nk % STG_S, gA, gB, m0, n0, Ks,
                                   nk, tid);
            asm volatile("cp.async.commit_group;");
            frags(32, 0);
            mmas(1);
            frags(48, 1);
            mmas(0);
            mmas(1);
        }
        asm volatile("cp.async.wait_group 0;");
        __syncthreads();
    }

    if (MODE == 0) {
        float* C = (float*)Cout;
#pragma unroll
        for (int mi = 0; mi < 4; mi++) {
            int r0 = m0 + wm * 64 + mi * 16 + gid;
#pragma unroll
            for (int ni = 0; ni < 8; ni++) {
                int c0 = n0 + wn * 64 + ni * 8 + tig * 2;
                float2 v0 = make_float2(acc[mi][ni][0] * INV_GEMM,
                                        acc[mi][ni][1] * INV_GEMM);
                float2 v1 = make_float2(acc[mi][ni][2] * INV_GEMM,
                                        acc[mi][ni][3] * INV_GEMM);
                *reinterpret_cast<float2*>(C + (size_t)r0 * N + c0) = v0;
                *reinterpret_cast<float2*>(C + (size_t)(r0 + 8) * N + c0) = v1;
            }
        }
    } else {
        // MODE 1: acc pair (c0,c1) = (gate,up) raw; local d = wn*32+ni*4+tig
        float* hs = reinterpret_cast<float*>(smem);   // [128][68] padded
#pragma unroll
        for (int mi = 0; mi < 4; mi++) {
            int rl = wm * 64 + mi * 16 + gid;
#pragma unroll
            for (int ni = 0; ni < 8; ni++) {
                int dl = wn * 32 + ni * 4 + tig;      // 0..63
                float g0 = acc[mi][ni][0] * INV_GEMM, u0 = acc[mi][ni][1] * INV_GEMM;
                hs[rl * 68 + dl]       = u0 * g0 / (1.0f + __expf(-g0));
                float g1 = acc[mi][ni][2] * INV_GEMM, u1 = acc[mi][ni][3] * INV_GEMM;
                hs[(rl + 8) * 68 + dl] = u1 * g1 / (1.0f + __expf(-g1));
            }
        }
        __syncthreads();
        __half* He = (__half*)Cout;
#pragma unroll
        for (int it = 0; it < 8; it++) {
            int rl  = it * 16 + (tid >> 3);
            int blk = tid & 7;
            float4 v0 = *reinterpret_cast<float4*>(&hs[rl * 68 + blk * 8]);
            float4 v1 = *reinterpret_cast<float4*>(&hs[rl * 68 + blk * 8 + 4]);
            float x[8] = {v0.x, v0.y, v0.z, v0.w, v1.x, v1.y, v1.z, v1.w};
            __half ob[8];
#pragma unroll
            for (int k = 0; k < 8; k++)
                ob[k] = __float2half_rn(x[k] * 16.0f);    // A-side scale
            *reinterpret_cast<uint4*>(
                He + (size_t)(m0 + rl) * K2P + (n0 + blk * 8)) =
                *reinterpret_cast<const uint4*>(ob);
        }
    }
}

// ============================================================================
// LoRA splitK kernel (proven 128x128, 8 warps 64x32, 256 thr): raw partials.
// ============================================================================
#define BM 128
#define STAGES 3
#define NTH 256
#define TILE_BYTES (BM * 64 * 2)               // 16 KB
#define SMEM_BYTES (2 * STAGES * TILE_BYTES)   // 96 KB

__device__ __forceinline__ void load_tiles_l(uint32_t smem_u32, int stage,
                                             const __half* gA,
                                             const __half* gB,
                                             int m0, int Ks, int kt, int tid) {
#pragma unroll
    for (int i = 0; i < 4; i++) {
        int c = tid + i * NTH;
        int row = c >> 3;
        int col = c & 7;
        uint32_t sw = (uint32_t)(col ^ (row & 7)) << 4;
        uint32_t da = smem_u32 + (uint32_t)stage * TILE_BYTES + row * 128 + sw;
        const void* sa = (const void*)(gA + (size_t)(m0 + row) * Ks
                                          + (size_t)kt * 64 + col * 8);
        asm volatile("cp.async.cg.shared.global [%0], [%1], 16;"
                     :: "r"(da), "l"(sa));
        int brow = row < RK ? row : RK - 1;     // clamp (N=64)
        uint32_t db = smem_u32 + (uint32_t)(STAGES + stage) * TILE_BYTES
                               + row * 128 + sw;
        const void* sb = (const void*)(gB + (size_t)brow * Ks
                                          + (size_t)kt * 64 + col * 8);
        asm volatile("cp.async.cg.shared.global [%0], [%1], 16;"
                     :: "r"(db), "l"(sb));
    }
}

__global__ __launch_bounds__(NTH, 2) void gemm_lora(
    const __half* __restrict__ A, const __half* __restrict__ B,
    float* __restrict__ Cout, int K) {
    extern __shared__ char smem[];
    const uint32_t smem_u32 = (uint32_t)__cvta_generic_to_shared(smem);
    const int tid  = threadIdx.x;
    const int warp = tid >> 5, lane = tid & 31;
    const int wm = warp >> 2, wn = warp & 3;
    const int gid = lane >> 2, tig = lane & 3;
    const int m0 = blockIdx.y * BM;

    float acc[4][4][4];
#pragma unroll
    for (int a = 0; a < 4; a++)
#pragma unroll
        for (int b = 0; b < 4; b++)
#pragma unroll
            for (int c = 0; c < 4; c++) acc[a][b][c] = 0.0f;

    const int a_row_in = (lane & 15);
    const int a_ch_in  = (lane >> 4);
    const int b_row_in = ((lane >> 4) << 3) + (lane & 7);
    const int b_ch_in  = ((lane >> 3) & 1);

    const int cps  = (K / 64) / SPLITK;
    const int koff = blockIdx.z * cps;

    for (int p = 0; p < STAGES - 1; p++) {
        if (p < cps)
            load_tiles_l(smem_u32, p, A, B, m0, K, koff + p, tid);
        asm volatile("cp.async.commit_group;");
    }
    for (int kt = 0; kt < cps; kt++) {
        asm volatile("cp.async.wait_group %0;" :: "n"(STAGES - 2));
        __syncthreads();
        int nk = kt + STAGES - 1;
        if (nk < cps)
            load_tiles_l(smem_u32, nk % STAGES, A, B, m0, K, koff + nk, tid);
        asm volatile("cp.async.commit_group;");

        const int st = kt % STAGES;
        const uint32_t sA = smem_u32 + (uint32_t)st * TILE_BYTES;
        const uint32_t sB = smem_u32 + (uint32_t)(STAGES + st) * TILE_BYTES;
#pragma unroll
        for (int kk = 0; kk < 64; kk += 16) {
            uint32_t ra[4][4], rb[4][2];
#pragma unroll
            for (int mi = 0; mi < 4; mi++) {
                int row = wm * 64 + mi * 16 + a_row_in;
                int ch  = (kk >> 3) + a_ch_in;
                uint32_t ad = sA + row * 128 + ((uint32_t)(ch ^ (row & 7)) << 4);
                asm volatile(
                    "ldmatrix.sync.aligned.m8n8.x4.shared.b16 {%0,%1,%2,%3}, [%4];"
                    : "=r"(ra[mi][0]), "=r"(ra[mi][1]),
                      "=r"(ra[mi][2]), "=r"(ra[mi][3])
                    : "r"(ad));
            }
#pragma unroll
            for (int p = 0; p < 2; p++) {
                int row = wn * 32 + p * 16 + b_row_in;
                int ch  = (kk >> 3) + b_ch_in;
                uint32_t bd = sB + row * 128 + ((uint32_t)(ch ^ (row & 7)) << 4);
                asm volatile(
                    "ldmatrix.sync.aligned.m8n8.x4.shared.b16 {%0,%1,%2,%3}, [%4];"
                    : "=r"(rb[2*p][0]), "=r"(rb[2*p][1]),
                      "=r"(rb[2*p+1][0]), "=r"(rb[2*p+1][1])
                    : "r"(bd));
            }
#pragma unroll
            for (int mi = 0; mi < 4; mi++)
#pragma unroll
                for (int ni = 0; ni < 4; ni++)
                    asm volatile(
                        "mma.sync.aligned.m16n8k16.row.col.f32.f16.f16.f32 "
                        "{%0,%1,%2,%3}, {%4,%5,%6,%7}, {%8,%9}, {%0,%1,%2,%3};"
                        : "+f"(acc[mi][ni][0]), "+f"(acc[mi][ni][1]),
                          "+f"(acc[mi][ni][2]), "+f"(acc[mi][ni][3])
                        : "r"(ra[mi][0]), "r"(ra[mi][1]),
                          "r"(ra[mi][2]), "r"(ra[mi][3]),
                          "r"(rb[ni][0]), "r"(rb[ni][1]));
        }
    }
    asm volatile("cp.async.wait_group 0;");
    __syncthreads();

    float* C = Cout + (size_t)blockIdx.z * MTOK * RK;
#pragma unroll
    for (int mi = 0; mi < 4; mi++) {
        int r0 = m0 + wm * 64 + mi * 16 + gid;
#pragma unroll
        for (int ni = 0; ni < 4; ni++) {
            int c0 = wn * 32 + ni * 8 + tig * 2;
            if (c0 < RK) {
                float2 v0 = make_float2(acc[mi][ni][0], acc[mi][ni][1]);
                float2 v1 = make_float2(acc[mi][ni][2], acc[mi][ni][3]);
                *reinterpret_cast<float2*>(C + (size_t)r0 * RK + c0) = v0;
                *reinterpret_cast<float2*>(C + (size_t)(r0 + 8) * RK + c0) = v1;
            }
        }
    }
}

// ---------------- launcher ---------------------------------------------------
extern "C" void kernel_launch(void* const* d_in, const int* in_sizes, int n_in,
                              void* d_out, int out_size) {
    const float* X   = (const float*)d_in[0];
    const float* Wgu = (const float*)d_in[1];
    const float* Agu = (const float*)d_in[2];
    const float* Bgu = (const float*)d_in[3];
    const float* Wd  = (const float*)d_in[4];
    const float* Ad  = (const float*)d_in[5];
    const float* Bd  = (const float*)d_in[6];
    float* out = (float*)d_out;

    __half *Xe, *Wgue, *Ague, *Bgue, *Wde, *Ade, *Bde, *T1e, *T2e, *He;
    float *Pk;
    cudaGetSymbolAddress((void**)&Xe,   g_Xe);
    cudaGetSymbolAddress((void**)&Wgue, g_Wgue);
    cudaGetSymbolAddress((void**)&Ague, g_Ague);
    cudaGetSymbolAddress((void**)&Bgue, g_Bgue);
    cudaGetSymbolAddress((void**)&Wde,  g_Wde);
    cudaGetSymbolAddress((void**)&Ade,  g_Ade);
    cudaGetSymbolAddress((void**)&Bde,  g_Bde);
    cudaGetSymbolAddress((void**)&Pk,   g_Pk);
    cudaGetSymbolAddress((void**)&T1e,  g_T1e);
    cudaGetSymbolAddress((void**)&T2e,  g_T2e);
    cudaGetSymbolAddress((void**)&He,   g_He);

    cudaFuncSetAttribute(gemm_sq<0>,
                         cudaFuncAttributeMaxDynamicSharedMemorySize, SMEM_S);
    cudaFuncSetAttribute(gemm_sq<1>,
                         cudaFuncAttributeMaxDynamicSharedMemorySize, SMEM_S);
    cudaFuncSetAttribute(gemm_lora,
                         cudaFuncAttributeMaxDynamicSharedMemorySize, SMEM_BYTES);

    const int T = 256;

    // ---- single launch for the 5 plain conversions ----
    CvtTab5 t5;
    t5.s[0] = { X,   Xe,   (size_t)MTOK * HID / 8,      16.0f };
    t5.s[1] = { Wgu, Wgue, (size_t)2 * DEX * HID / 8,   64.0f };
    t5.s[2] = { Agu, Ague, (size_t)RK * HID / 8,        64.0f };
    t5.s[3] = { Wd,  Wde,  (size_t)HID * DEX / 8,       64.0f };
    t5.s[4] = { Ad,  Ade,  (size_t)RK * DEX / 8,        64.0f };
    t5.cum8[0] = 0;
    for (int k = 0; k < 5; k++) t5.cum8[k+1] = t5.cum8[k] + t5.s[k].n8;
    cvt_plain_multi<<<(unsigned)((t5.cum8[5] + T - 1) / T), T>>>(t5);

    // ---- single launch for the 2 B-tail expansions ----
    CvtTab2 t2;
    t2.s[0] = { Bgu, Bgue, (size_t)2 * DEX * RK / 8, 64.0f };
    t2.s[1] = { Bd,  Bde,  (size_t)HID * RK / 8,     64.0f };
    t2.cum8[0] = 0;
    t2.cum8[1] = t2.s[0].n8;
    t2.cum8[2] = t2.cum8[1] + t2.s[1].n8;
    cvt_expand_multi<<<(unsigned)((t2.cum8[2] + T - 1) / T), T>>>(t2);

    const unsigned gr = (unsigned)(((size_t)MTOK * RK + T - 1) / T);

    // T1 raw = 1024*(X @ Agu^T), splitK x4 -> reduce(/256) -> T1e pairs
    gemm_lora<<<dim3(1, MTOK/BM, SPLITK), NTH, SMEM_BYTES>>>(Xe, Ague, Pk, K1P);
    reduce_expand<<<gr, T>>>(Pk, T1e);

    // He = 16*swiglu(X@Wgu^T + 0.25*T1@Bgu^T), plain fp16 (square 64x64 warps)
    gemm_sq<1><<<dim3(DEX/64, MTOK/BMS), NTH_S, SMEM_S>>>(
        Xe, Wgue, T1e, Bgue, He, 2*DEX, K1P, KRE);

    // T2 raw = 1024*(H @ Ad^T), splitK x4 -> reduce -> T2e
    gemm_lora<<<dim3(1, MTOK/BM, SPLITK), NTH, SMEM_BYTES>>>(He, Ade, Pk, K2P);
    reduce_expand<<<gr, T>>>(Pk, T2e);

    // out = H@Wd^T + 0.25*T2@Bd^T (square 64x64 warps)
    gemm_sq<0><<<dim3(HID/BNS, MTOK/BMS), NTH_S, SMEM_S>>>(
        He, Wde, T2e, Bde, out, HID, K2P, KRE);
}

// round 15
// speedup vs baseline: 1.1709x; 1.0225x over previous
#include <cuda_runtime.h>
#include <cuda_fp16.h>
#include <cstdint>

#define MTOK 8192
#define HID  2048
#define DEX  4096
#define RK   64
#define K1P  HID       // 2048  GEMM1 K (plain fp16 both sides)
#define K2P  DEX       // 4096  GEMM2 K (plain fp16 both sides)
#define KRE  (2*RK)    // 128   LoRA tail K (split pairs)
#define SPLITK 4
// scaling: A-side stored = 16*true, B-side = 64*true, GEMM raw = 1024*true
#define INV_GEMM (1.0f/1024.0f)

// ---------------- scratch (device globals) ----------------------------------
__device__ __align__(16) __half g_Xe  [(size_t)MTOK * K1P];
__device__ __align__(16) __half g_Wgue[(size_t)2*DEX * K1P];
__device__ __align__(16) __half g_Ague[(size_t)RK * K1P];
__device__ __align__(16) __half g_Bgue[(size_t)2*DEX * KRE];
__device__ __align__(16) __half g_Wde [(size_t)HID * K2P];
__device__ __align__(16) __half g_Ade [(size_t)RK * K2P];
__device__ __align__(16) __half g_Bde [(size_t)HID * KRE];
__device__ __align__(16) float  g_Pk  [(size_t)SPLITK * MTOK * RK];
__device__ __align__(16) __half g_T1e [(size_t)MTOK * KRE];
__device__ __align__(16) __half g_T2e [(size_t)MTOK * KRE];
__device__ __align__(16) __half g_He  [(size_t)MTOK * K2P];

// ---------------- all conversions in one launch ------------------------------
// dup=0: plain fp16 (8 in -> 8 out). dup=1: B-dup pairs (8 in -> 16 out).
struct CvtSeg { const float* in; __half* out; size_t n8; float scale; int dup; };
struct CvtTab { CvtSeg s[7]; size_t cum8[8]; };

__global__ void cvt_all(CvtTab tab) {
    size_t i = (size_t)blockIdx.x * blockDim.x + threadIdx.x;
    if (i >= tab.cum8[7]) return;
    int sidx = 0;
#pragma unroll
    for (int k = 1; k < 7; k++) sidx += (i >= tab.cum8[k]) ? 1 : 0;
    const CvtSeg sg = tab.s[sidx];
    size_t j = i - tab.cum8[sidx];
    const float4* p = reinterpret_cast<const float4*>(sg.in) + j * 2;
    float4 v0 = p[0], v1 = p[1];
    float x[8] = {v0.x, v0.y, v0.z, v0.w, v1.x, v1.y, v1.z, v1.w};
    if (!sg.dup) {
        __half ob[8];
#pragma unroll
        for (int k = 0; k < 8; k++) ob[k] = __float2half_rn(x[k] * sg.scale);
        *reinterpret_cast<uint4*>(sg.out + j * 8) =
            *reinterpret_cast<const uint4*>(ob);
    } else {
        __half ob[16];
#pragma unroll
        for (int k = 0; k < 8; k++) {
            __half hi = __float2half_rn(x[k] * sg.scale);
            ob[2*k] = hi; ob[2*k+1] = hi;
        }
        uint4* o = reinterpret_cast<uint4*>(sg.out + j * 16);
        const uint4* s = reinterpret_cast<const uint4*>(ob);
        o[0] = s[0]; o[1] = s[1];
    }
}

// ---------------- splitK reduce + scale + A-side fp16 pair (x4 vec) ---------
__global__ void reduce_expand4(const float* __restrict__ P,
                               __half* __restrict__ out) {
    size_t q = (size_t)blockIdx.x * blockDim.x + threadIdx.x;
    if (q >= (size_t)MTOK * RK / 4) return;
    const size_t S = (size_t)MTOK * RK;
    size_t base = q * 4;
    float4 a = *reinterpret_cast<const float4*>(P + base);
    float4 b = *reinterpret_cast<const float4*>(P + S + base);
    float4 c = *reinterpret_cast<const float4*>(P + 2*S + base);
    float4 d = *reinterpret_cast<const float4*>(P + 3*S + base);
    float s[4] = {(a.x+b.x+c.x+d.x) * (1.0f/256.0f),
                  (a.y+b.y+c.y+d.y) * (1.0f/256.0f),
                  (a.z+b.z+c.z+d.z) * (1.0f/256.0f),
                  (a.w+b.w+c.w+d.w) * (1.0f/256.0f)};
    __half ob[8];
#pragma unroll
    for (int k = 0; k < 4; k++) {
        __half hi = __float2half_rn(s[k]);
        ob[2*k]   = hi;
        ob[2*k+1] = __float2half_rn(s[k] - __half2float(hi));
    }
    *reinterpret_cast<uint4*>(out + base * 2) =
        *reinterpret_cast<const uint4*>(ob);
}

// ============================================================================
// SQ kernel: CTA 128x128, 4 warps (2x2) of 64x64, 128 threads, 2 CTAs/SM,
// double-buffered fragments.  MODE 0: C fp32 (descaled) + LoRA tail.
// MODE 1: fused SwiGLU -> He plain fp16 (x16), gate/up interleaved B rows.
// ============================================================================
#define BMS 128
#define BNS 128
#define STG_S 3
#define NTH_S 128
#define TILE_S (128 * 64 * 2)                  // 16 KB
#define SMEM_S (2 * STG_S * TILE_S)            // 96 KB

template<int MODE>
__device__ __forceinline__ void load_tiles_s(uint32_t smem_u32, int stage,
                                             const __half* gA,
                                             const __half* gB,
                                             int m0, int n0, int Ks,
                                             int kt, int tid) {
#pragma unroll
    for (int i = 0; i < 8; i++) {
        int c = tid + i * NTH_S;        // 0..1023 16B chunks per operand
        int row = c >> 3;
        int col = c & 7;
        uint32_t sw = (uint32_t)(col ^ (row & 7)) << 4;
        uint32_t da = smem_u32 + (uint32_t)stage * TILE_S + row * 128 + sw;
        const void* sa = (const void*)(gA + (size_t)(m0 + row) * Ks
                                          + (size_t)kt * 64 + col * 8);
        asm volatile("cp.async.cg.shared.global [%0], [%1], 16;"
                     :: "r"(da), "l"(sa));
        int brow;
        if (MODE == 1) {                // gate/up interleave; n0 = d-offset
            brow = (row & 1) ? (DEX + n0 + (row >> 1)) : (n0 + (row >> 1));
        } else {
            brow = n0 + row;
        }
        uint32_t db = smem_u32 + (uint32_t)(STG_S + stage) * TILE_S
                               + row * 128 + sw;
        const void* sb = (const void*)(gB + (size_t)brow * Ks
                                          + (size_t)kt * 64 + col * 8);
        asm volatile("cp.async.cg.shared.global [%0], [%1], 16;"
                     :: "r"(db), "l"(sb));
    }
}

template<int MODE>
__global__ __launch_bounds__(NTH_S, 2) void gemm_sq(
    const __half* __restrict__ A,  const __half* __restrict__ B,
    const __half* __restrict__ A2, const __half* __restrict__ B2,
    void* __restrict__ Cout, int N, int K, int Kt) {
    extern __shared__ char smem[];
    const uint32_t smem_u32 = (uint32_t)__cvta_generic_to_shared(smem);
    const int tid  = threadIdx.x;
    const int warp = tid >> 5, lane = tid & 31;
    const int wm = warp >> 1, wn = warp & 1;   // 2x2 warps of 64x64
    const int gid = lane >> 2, tig = lane & 3;

    // grouped CTA swizzle (8 y-tiles per x step) for L2 reuse of B panels
    int bx = blockIdx.x, by = blockIdx.y;
    if (gridDim.x > 1) {
        const int GRP = 8;
        int lin = by * gridDim.x + bx;
        int per = gridDim.x * GRP;
        int g   = lin / per, rem = lin % per;
        int gy  = g * GRP;
        int h   = gridDim.y - gy; if (h > GRP) h = GRP;
        by = gy + rem % h;
        bx = rem / h;
    }
    const int m0 = by * BMS;
    const int n0 = bx * ((MODE == 1) ? 64 : BNS);

    float acc[4][8][4];
#pragma unroll
    for (int a = 0; a < 4; a++)
#pragma unroll
        for (int b = 0; b < 8; b++)
#pragma unroll
            for (int c = 0; c < 4; c++) acc[a][b][c] = 0.0f;

    const int a_row_in = (lane & 15);
    const int a_ch_in  = (lane >> 4);
    const int b_row_in = ((lane >> 4) << 3) + (lane & 7);
    const int b_ch_in  = ((lane >> 3) & 1);

    for (int seg = 0; seg < 2; seg++) {
        const __half* gA = seg ? A2 : A;
        const __half* gB = seg ? B2 : B;
        const int Ks = seg ? Kt : K;
        if (Ks == 0) break;
        const int ktiles = Ks / 64;

        for (int p = 0; p < STG_S - 1; p++) {
            if (p < ktiles)
                load_tiles_s<MODE>(smem_u32, p, gA, gB, m0, n0, Ks, p, tid);
            asm volatile("cp.async.commit_group;");
        }

        for (int kt = 0; kt < ktiles; kt++) {
            asm volatile("cp.async.wait_group %0;" :: "n"(STG_S - 2));
            __syncthreads();

            const int st = kt % STG_S;
            const uint32_t sA = smem_u32 + (uint32_t)st * TILE_S;
            const uint32_t sB = smem_u32 + (uint32_t)(STG_S + st) * TILE_S;

            uint32_t ra[2][4][4], rb[2][8][2];
            auto frags = [&](int kk, int buf) {
#pragma unroll
                for (int mi = 0; mi < 4; mi++) {
                    int row = wm * 64 + mi * 16 + a_row_in;
                    int ch  = (kk >> 3) + a_ch_in;
                    uint32_t ad = sA + row * 128 + ((uint32_t)(ch ^ (row & 7)) << 4);
                    asm volatile(
                        "ldmatrix.sync.aligned.m8n8.x4.shared.b16 {%0,%1,%2,%3}, [%4];"
                        : "=r"(ra[buf][mi][0]), "=r"(ra[buf][mi][1]),
                          "=r"(ra[buf][mi][2]), "=r"(ra[buf][mi][3])
                        : "r"(ad));
                }
#pragma unroll
                for (int p = 0; p < 4; p++) {
                    int row = wn * 64 + p * 16 + b_row_in;
                    int ch  = (kk >> 3) + b_ch_in;
                    uint32_t bd = sB + row * 128 + ((uint32_t)(ch ^ (row & 7)) << 4);
                    asm volatile(
                        "ldmatrix.sync.aligned.m8n8.x4.shared.b16 {%0,%1,%2,%3}, [%4];"
                        : "=r"(rb[buf][2*p][0]), "=r"(rb[buf][2*p][1]),
                          "=r"(rb[buf][2*p+1][0]), "=r"(rb[buf][2*p+1][1])
                        : "r"(bd));
                }
            };
            auto mmas = [&](int buf) {
#pragma unroll
                for (int mi = 0; mi < 4; mi++)
#pragma unroll
                    for (int ni = 0; ni < 8; ni++)
                        asm volatile(
                            "mma.sync.aligned.m16n8k16.row.col.f32.f16.f16.f32 "
                            "{%0,%1,%2,%3}, {%4,%5,%6,%7}, {%8,%9}, {%0,%1,%2,%3};"
                            : "+f"(acc[mi][ni][0]), "+f"(acc[mi][ni][1]),
                              "+f"(acc[mi][ni][2]), "+f"(acc[mi][ni][3])
                            : "r"(ra[buf][mi][0]), "r"(ra[buf][mi][1]),
                              "r"(ra[buf][mi][2]), "r"(ra[buf][mi][3]),
                              "r"(rb[buf][ni][0]), "r"(rb[buf][ni][1]));
            };

            frags(0, 0);
            frags(16, 1);
            mmas(0);
            int nk = kt + STG_S - 1;
            if (nk < ktiles)
                load_tiles_s<MODE>(smem_u32, nk % STG_S, gA, gB, m0, n0, Ks,
                                   nk, tid);
            asm volatile("cp.async.commit_group;");
            frags(32, 0);
            mmas(1);
            frags(48, 1);
            mmas(0);
            mmas(1);
        }
        asm volatile("cp.async.wait_group 0;");
        __syncthreads();
    }

    if (MODE == 0) {
        float* C = (float*)Cout;
#pragma unroll
        for (int mi = 0; mi < 4; mi++) {
            int r0 = m0 + wm * 64 + mi * 16 + gid;
#pragma unroll
            for (int ni = 0; ni < 8; ni++) {
                int c0 = n0 + wn * 64 + ni * 8 + tig * 2;
                float2 v0 = make_float2(acc[mi][ni][0] * INV_GEMM,
                                        acc[mi][ni][1] * INV_GEMM);
                float2 v1 = make_float2(acc[mi][ni][2] * INV_GEMM,
                                        acc[mi][ni][3] * INV_GEMM);
                *reinterpret_cast<float2*>(C + (size_t)r0 * N + c0) = v0;
                *reinterpret_cast<float2*>(C + (size_t)(r0 + 8) * N + c0) = v1;
            }
        }
    } else {
        // MODE 1: acc pair (c0,c1) = (gate,up) raw; local d = wn*32+ni*4+tig
        float* hs = reinterpret_cast<float*>(smem);   // [128][68] padded
#pragma unroll
        for (int mi = 0; mi < 4; mi++) {
            int rl = wm * 64 + mi * 16 + gid;
#pragma unroll
            for (int ni = 0; ni < 8; ni++) {
                int dl = wn * 32 + ni * 4 + tig;      // 0..63
                float g0 = acc[mi][ni][0] * INV_GEMM, u0 = acc[mi][ni][1] * INV_GEMM;
                hs[rl * 68 + dl]       = u0 * g0 / (1.0f + __expf(-g0));
                float g1 = acc[mi][ni][2] * INV_GEMM, u1 = acc[mi][ni][3] * INV_GEMM;
                hs[(rl + 8) * 68 + dl] = u1 * g1 / (1.0f + __expf(-g1));
            }
        }
        __syncthreads();
        __half* He = (__half*)Cout;
#pragma unroll
        for (int it = 0; it < 8; it++) {
            int rl  = it * 16 + (tid >> 3);
            int blk = tid & 7;
            float4 v0 = *reinterpret_cast<float4*>(&hs[rl * 68 + blk * 8]);
            float4 v1 = *reinterpret_cast<float4*>(&hs[rl * 68 + blk * 8 + 4]);
            float x[8] = {v0.x, v0.y, v0.z, v0.w, v1.x, v1.y, v1.z, v1.w};
            __half ob[8];
#pragma unroll
            for (int k = 0; k < 8; k++)
                ob[k] = __float2half_rn(x[k] * 16.0f);    // A-side scale
            *reinterpret_cast<uint4*>(
                He + (size_t)(m0 + rl) * K2P + (n0 + blk * 8)) =
                *reinterpret_cast<const uint4*>(ob);
        }
    }
}

// ============================================================================
// LoRA splitK kernel: CTA 128x64, 4 warps (2x2) of 64x32, 128 threads.
// B tile only 64 rows (8 KB/stage). Raw partials to Pk[split].
// ============================================================================
#define BM_L 128
#define STG_L 3
#define NTH_L 128
#define ATILE_L (128 * 64 * 2)                 // 16 KB
#define BTILE_L (64 * 64 * 2)                  // 8 KB
#define SMEM_L (STG_L * (ATILE_L + BTILE_L))   // 72 KB -> 2 CTAs/SM

__device__ __forceinline__ void load_tiles_l(uint32_t smem_u32, int stage,
                                             const __half* gA,
                                             const __half* gB,
                                             int m0, int Ks, int kt, int tid) {
#pragma unroll
    for (int i = 0; i < 12; i++) {      // 1024 A + 512 B chunks, 128 thr
        int c = tid + i * NTH_L;
        if (c < 1024) {
            int row = c >> 3, col = c & 7;
            uint32_t sw = (uint32_t)(col ^ (row & 7)) << 4;
            uint32_t da = smem_u32 + (uint32_t)stage * ATILE_L + row * 128 + sw;
            const void* sa = (const void*)(gA + (size_t)(m0 + row) * Ks
                                              + (size_t)kt * 64 + col * 8);
            asm volatile("cp.async.cg.shared.global [%0], [%1], 16;"
                         :: "r"(da), "l"(sa));
        } else {
            int b = c - 1024;
            int row = b >> 3, col = b & 7;   // row 0..63
            uint32_t sw = (uint32_t)(col ^ (row & 7)) << 4;
            uint32_t db = smem_u32 + (uint32_t)(STG_L * ATILE_L)
                                   + (uint32_t)stage * BTILE_L + row * 128 + sw;
            const void* sb = (const void*)(gB + (size_t)row * Ks
                                              + (size_t)kt * 64 + col * 8);
            asm volatile("cp.async.cg.shared.global [%0], [%1], 16;"
                         :: "r"(db), "l"(sb));
        }
    }
}

__global__ __launch_bounds__(NTH_L, 2) void gemm_lora(
    const __half* __restrict__ A, const __half* __restrict__ B,
    float* __restrict__ Cout, int K) {
    extern __shared__ char smem[];
    const uint32_t smem_u32 = (uint32_t)__cvta_generic_to_shared(smem);
    const int tid  = threadIdx.x;
    const int warp = tid >> 5, lane = tid & 31;
    const int wm = warp >> 1, wn = warp & 1;   // 2x2 warps of 64x32
    const int gid = lane >> 2, tig = lane & 3;
    const int m0 = blockIdx.y * BM_L;

    float acc[4][4][4];
#pragma unroll
    for (int a = 0; a < 4; a++)
#pragma unroll
        for (int b = 0; b < 4; b++)
#pragma unroll
            for (int c = 0; c < 4; c++) acc[a][b][c] = 0.0f;

    const int a_row_in = (lane & 15);
    const int a_ch_in  = (lane >> 4);
    const int b_row_in = ((lane >> 4) << 3) + (lane & 7);
    const int b_ch_in  = ((lane >> 3) & 1);

    const int cps  = (K / 64) / SPLITK;
    const int koff = blockIdx.z * cps;

    for (int p = 0; p < STG_L - 1; p++) {
        if (p < cps)
            load_tiles_l(smem_u32, p, A, B, m0, K, koff + p, tid);
        asm volatile("cp.async.commit_group;");
    }
    for (int kt = 0; kt < cps; kt++) {
        asm volatile("cp.async.wait_group %0;" :: "n"(STG_L - 2));
        __syncthreads();
        int nk = kt + STG_L - 1;
        if (nk < cps)
            load_tiles_l(smem_u32, nk % STG_L, A, B, m0, K, koff + nk, tid);
        asm volatile("cp.async.commit_group;");

        const int st = kt % STG_L;
        const uint32_t sA = smem_u32 + (uint32_t)st * ATILE_L;
        const uint32_t sB = smem_u32 + (uint32_t)(STG_L * ATILE_L)
                                     + (uint32_t)st * BTILE_L;
#pragma unroll
        for (int kk = 0; kk < 64; kk += 16) {
            uint32_t ra[4][4], rb[4][2];
#pragma unroll
            for (int mi = 0; mi < 4; mi++) {
                int row = wm * 64 + mi * 16 + a_row_in;
                int ch  = (kk >> 3) + a_ch_in;
                uint32_t ad = sA + row * 128 + ((uint32_t)(ch ^ (row & 7)) << 4);
                asm volatile(
                    "ldmatrix.sync.aligned.m8n8.x4.shared.b16 {%0,%1,%2,%3}, [%4];"
                    : "=r"(ra[mi][0]), "=r"(ra[mi][1]),
                      "=r"(ra[mi][2]), "=r"(ra[mi][3])
                    : "r"(ad));
            }
#pragma unroll
            for (int p = 0; p < 2; p++) {
                int row = wn * 32 + p * 16 + b_row_in;   // 0..63
                int ch  = (kk >> 3) + b_ch_in;
                uint32_t bd = sB + row * 128 + ((uint32_t)(ch ^ (row & 7)) << 4);
                asm volatile(
                    "ldmatrix.sync.aligned.m8n8.x4.shared.b16 {%0,%1,%2,%3}, [%4];"
                    : "=r"(rb[2*p][0]), "=r"(rb[2*p][1]),
                      "=r"(rb[2*p+1][0]), "=r"(rb[2*p+1][1])
                    : "r"(bd));
            }
#pragma unroll
            for (int mi = 0; mi < 4; mi++)
#pragma unroll
                for (int ni = 0; ni < 4; ni++)
                    asm volatile(
                        "mma.sync.aligned.m16n8k16.row.col.f32.f16.f16.f32 "
                        "{%0,%1,%2,%3}, {%4,%5,%6,%7}, {%8,%9}, {%0,%1,%2,%3};"
                        : "+f"(acc[mi][ni][0]), "+f"(acc[mi][ni][1]),
                          "+f"(acc[mi][ni][2]), "+f"(acc[mi][ni][3])
                        : "r"(ra[mi][0]), "r"(ra[mi][1]),
                          "r"(ra[mi][2]), "r"(ra[mi][3]),
                          "r"(rb[ni][0]), "r"(rb[ni][1]));
        }
    }
    asm volatile("cp.async.wait_group 0;");
    __syncthreads();

    float* C = Cout + (size_t)blockIdx.z * MTOK * RK;
#pragma unroll
    for (int mi = 0; mi < 4; mi++) {
        int r0 = m0 + wm * 64 + mi * 16 + gid;
#pragma unroll
        for (int ni = 0; ni < 4; ni++) {
            int c0 = wn * 32 + ni * 8 + tig * 2;   // 0..63 always valid
            float2 v0 = make_float2(acc[mi][ni][0], acc[mi][ni][1]);
            float2 v1 = make_float2(acc[mi][ni][2], acc[mi][ni][3]);
            *reinterpret_cast<float2*>(C + (size_t)r0 * RK + c0) = v0;
            *reinterpret_cast<float2*>(C + (size_t)(r0 + 8) * RK + c0) = v1;
        }
    }
}

// ---------------- launcher ---------------------------------------------------
extern "C" void kernel_launch(void* const* d_in, const int* in_sizes, int n_in,
                              void* d_out, int out_size) {
    const float* X   = (const float*)d_in[0];
    const float* Wgu = (const float*)d_in[1];
    const float* Agu = (const float*)d_in[2];
    const float* Bgu = (const float*)d_in[3];
    const float* Wd  = (const float*)d_in[4];
    const float* Ad  = (const float*)d_in[5];
    const float* Bd  = (const float*)d_in[6];
    float* out = (float*)d_out;

    __half *Xe, *Wgue, *Ague, *Bgue, *Wde, *Ade, *Bde, *T1e, *T2e, *He;
    float *Pk;
    cudaGetSymbolAddress((void**)&Xe,   g_Xe);
    cudaGetSymbolAddress((void**)&Wgue, g_Wgue);
    cudaGetSymbolAddress((void**)&Ague, g_Ague);
    cudaGetSymbolAddress((void**)&Bgue, g_Bgue);
    cudaGetSymbolAddress((void**)&Wde,  g_Wde);
    cudaGetSymbolAddress((void**)&Ade,  g_Ade);
    cudaGetSymbolAddress((void**)&Bde,  g_Bde);
    cudaGetSymbolAddress((void**)&Pk,   g_Pk);
    cudaGetSymbolAddress((void**)&T1e,  g_T1e);
    cudaGetSymbolAddress((void**)&T2e,  g_T2e);
    cudaGetSymbolAddress((void**)&He,   g_He);

    cudaFuncSetAttribute(gemm_sq<0>,
                         cudaFuncAttributeMaxDynamicSharedMemorySize, SMEM_S);
    cudaFuncSetAttribute(gemm_sq<1>,
                         cudaFuncAttributeMaxDynamicSharedMemorySize, SMEM_S);
    cudaFuncSetAttribute(gemm_lora,
                         cudaFuncAttributeMaxDynamicSharedMemorySize, SMEM_L);

    const int T = 256;

    // ---- all 7 conversions in one launch ----
    CvtTab tb;
    tb.s[0] = { X,   Xe,   (size_t)MTOK * HID / 8,    16.0f, 0 };
    tb.s[1] = { Wgu, Wgue, (size_t)2 * DEX * HID / 8, 64.0f, 0 };
    tb.s[2] = { Agu, Ague, (size_t)RK * HID / 8,      64.0f, 0 };
    tb.s[3] = { Wd,  Wde,  (size_t)HID * DEX / 8,     64.0f, 0 };
    tb.s[4] = { Ad,  Ade,  (size_t)RK * DEX / 8,      64.0f, 0 };
    tb.s[5] = { Bgu, Bgue, (size_t)2 * DEX * RK / 8,  64.0f, 1 };
    tb.s[6] = { Bd,  Bde,  (size_t)HID * RK / 8,      64.0f, 1 };
    tb.cum8[0] = 0;
    for (int k = 0; k < 7; k++) tb.cum8[k+1] = tb.cum8[k] + tb.s[k].n8;
    cvt_all<<<(unsigned)((tb.cum8[7] + T - 1) / T), T>>>(tb);

    const unsigned gr4 = (unsigned)(((size_t)MTOK * RK / 4 + T - 1) / T);

    // T1 raw = 1024*(X @ Agu^T), splitK x4 -> reduce(/256) -> T1e pairs
    gemm_lora<<<dim3(1, MTOK/BM_L, SPLITK), NTH_L, SMEM_L>>>(Xe, Ague, Pk, K1P);
    reduce_expand4<<<gr4, T>>>(Pk, T1e);

    // He = 16*swiglu(X@Wgu^T + 0.25*T1@Bgu^T), plain fp16 (square 64x64 warps)
    gemm_sq<1><<<dim3(DEX/64, MTOK/BMS), NTH_S, SMEM_S>>>(
        Xe, Wgue, T1e, Bgue, He, 2*DEX, K1P, KRE);

    // T2 raw = 1024*(H @ Ad^T), splitK x4 -> reduce -> T2e
    gemm_lora<<<dim3(1, MTOK/BM_L, SPLITK), NTH_L, SMEM_L>>>(He, Ade, Pk, K2P);
    reduce_expand4<<<gr4, T>>>(Pk, T2e);

    // out = H@Wd^T + 0.25*T2@Bd^T (square 64x64 warps)
    gemm_sq<0><<<dim3(HID/BNS, MTOK/BMS), NTH_S, SMEM_S>>>(
        He, Wde, T2e, Bde, out, HID, K2P, KRE);
}